// round 2
// baseline (speedup 1.0000x reference)
#include <cuda_runtime.h>
#include <math.h>

#define H_DIM  1024
#define NHEADS 16
#define HEAD   64
#define BATCH  2
#define SEQ    2048
#define MROWS  (BATCH * SEQ)          // 4096
#define SCALE  0.03125f               // 1/sqrt(1024)

typedef unsigned long long ull;

// Packed f32x2 helpers (sm_100+ PTX; SASS FFMA2 — 2x fp32 FMA per instruction)
__device__ __forceinline__ ull ffma2(ull a, ull b, ull c) {
    ull d;
    asm("fma.rn.f32x2 %0, %1, %2, %3;" : "=l"(d) : "l"(a), "l"(b), "l"(c));
    return d;
}
__device__ __forceinline__ ull fmul2(ull a, ull b) {
    ull d;
    asm("mul.rn.f32x2 %0, %1, %2;" : "=l"(d) : "l"(a), "l"(b));
    return d;
}
__device__ __forceinline__ ull dup2(float x) {
    ull d;
    asm("mov.b64 %0, {%1, %1};" : "=l"(d) : "f"(x));
    return d;
}
__device__ __forceinline__ float2 unpack2(ull v) {
    float2 r;
    asm("mov.b64 {%0, %1}, %2;" : "=f"(r.x), "=f"(r.y) : "l"(v));
    return r;
}

// Scratch for projected Q, K, V  ([B*T, H_DIM] row-major each)
__device__ float g_q[MROWS * H_DIM];
__device__ float g_k[MROWS * H_DIM];
__device__ float g_v[MROWS * H_DIM];

// ---------------------------------------------------------------------------
// Kernel 1: fused QKV projection.  out[m,n] = sum_k x[m,k]*W[n,k] + b[n]
// 64x64 block tile, 4x4 register tile per thread (as 4x2 f32x2 pairs), BK=16.
// ---------------------------------------------------------------------------
__global__ __launch_bounds__(256) void qkv_gemm_kernel(
    const float* __restrict__ x,
    const float* __restrict__ Wq, const float* __restrict__ bq,
    const float* __restrict__ Wk, const float* __restrict__ bk,
    const float* __restrict__ Wv, const float* __restrict__ bv)
{
    const int which = blockIdx.z;
    const float* W    = (which == 0) ? Wq : (which == 1) ? Wk : Wv;
    const float* bias = (which == 0) ? bq : (which == 1) ? bk : bv;
    float*       out  = (which == 0) ? g_q : (which == 1) ? g_k : g_v;

    __shared__ float As[16][68];   // [k][m], padded (rows stay 16B-aligned)
    __shared__ float Bs[16][68];   // [k][n]

    const int tid = threadIdx.x;           // 0..255
    const int tx  = tid & 15;              // n sub-tile
    const int ty  = tid >> 4;              // m sub-tile
    const int m0  = blockIdx.y * 64;
    const int n0  = blockIdx.x * 64;

    ull acc[4][2] = {};                    // 4 m-rows x 2 packed n-pairs

    const int lr = tid >> 2;               // 0..63 (row within tile)
    const int lc = (tid & 3) * 4;          // 0,4,8,12 (k offset)

    for (int k0 = 0; k0 < H_DIM; k0 += 16) {
        float4 a = *(const float4*)&x[(size_t)(m0 + lr) * H_DIM + k0 + lc];
        float4 b = *(const float4*)&W[(size_t)(n0 + lr) * H_DIM + k0 + lc];
        As[lc + 0][lr] = a.x; As[lc + 1][lr] = a.y;
        As[lc + 2][lr] = a.z; As[lc + 3][lr] = a.w;
        Bs[lc + 0][lr] = b.x; Bs[lc + 1][lr] = b.y;
        Bs[lc + 2][lr] = b.z; Bs[lc + 3][lr] = b.w;
        __syncthreads();

        #pragma unroll
        for (int kk = 0; kk < 16; kk++) {
            float4 av = *(const float4*)&As[kk][ty * 4];      // LDS.128
            ulonglong2 bv2 = *(const ulonglong2*)&Bs[kk][tx * 4]; // LDS.128: 2 packed pairs
            ull d0 = dup2(av.x), d1 = dup2(av.y), d2 = dup2(av.z), d3 = dup2(av.w);
            acc[0][0] = ffma2(d0, bv2.x, acc[0][0]);
            acc[0][1] = ffma2(d0, bv2.y, acc[0][1]);
            acc[1][0] = ffma2(d1, bv2.x, acc[1][0]);
            acc[1][1] = ffma2(d1, bv2.y, acc[1][1]);
            acc[2][0] = ffma2(d2, bv2.x, acc[2][0]);
            acc[2][1] = ffma2(d2, bv2.y, acc[2][1]);
            acc[3][0] = ffma2(d3, bv2.x, acc[3][0]);
            acc[3][1] = ffma2(d3, bv2.y, acc[3][1]);
        }
        __syncthreads();
    }

    const int n = n0 + tx * 4;
    const float4 bia = *(const float4*)&bias[n];
    #pragma unroll
    for (int i = 0; i < 4; i++) {
        const int m = m0 + ty * 4 + i;
        float2 p0 = unpack2(acc[i][0]);
        float2 p1 = unpack2(acc[i][1]);
        float4 r = make_float4(p0.x + bia.x, p0.y + bia.y, p1.x + bia.z, p1.y + bia.w);
        *(float4*)&out[(size_t)m * H_DIM + n] = r;
    }
}

// ---------------------------------------------------------------------------
// Kernel 2: causal attention per (b, h, 64-row q tile).
// 64 threads: thread t owns query row qt*64+t. Online softmax, K/V in smem,
// all inner FMAs packed f32x2.
// ---------------------------------------------------------------------------
__global__ __launch_bounds__(64) void attn_kernel(float* __restrict__ out)
{
    const int qt  = blockIdx.x;            // 0..31  (q tile)
    const int bh  = blockIdx.y;            // 0..31  (batch*head)
    const int tid = threadIdx.x;           // 0..63
    const int b   = bh >> 4;
    const int h   = bh & 15;

    const int qrow = qt * 64 + tid;
    const size_t base = ((size_t)(b * SEQ)) * H_DIM + h * HEAD;

    // q row in registers: 32 packed pairs
    ull q2[32];
    {
        const ulonglong2* qp = (const ulonglong2*)&g_q[base + (size_t)qrow * H_DIM];
        #pragma unroll
        for (int i = 0; i < 16; i++) {
            ulonglong2 v = qp[i];
            q2[2 * i]     = v.x;
            q2[2 * i + 1] = v.y;
        }
    }

    ull o2[32];
    #pragma unroll
    for (int i = 0; i < 32; i++) o2[i] = 0ull;
    float mmax = -1e30f, l = 0.f;

    __shared__ float4 Ks[64][17];          // padded rows (16B-aligned)
    __shared__ float4 Vs[64][17];

    for (int kt = 0; kt <= qt; kt++) {
        __syncthreads();
        const int krow = kt * 64 + tid;
        const float4* kp = (const float4*)&g_k[base + (size_t)krow * H_DIM];
        const float4* vp = (const float4*)&g_v[base + (size_t)krow * H_DIM];
        #pragma unroll
        for (int i = 0; i < 16; i++) {
            Ks[tid][i] = kp[i];
            Vs[tid][i] = vp[i];
        }
        __syncthreads();

        const int jmax = (kt == qt) ? tid : 63;
        for (int j = 0; j <= jmax; j++) {
            const ulonglong2* kr = (const ulonglong2*)&Ks[j][0];
            // s = q . K[j]   (4 packed accumulator chains)
            ull sa = 0ull, sb = 0ull, sc = 0ull, sd = 0ull;
            #pragma unroll
            for (int i = 0; i < 16; i += 2) {
                ulonglong2 k0 = kr[i];
                ulonglong2 k1 = kr[i + 1];
                sa = ffma2(q2[2 * i],     k0.x, sa);
                sb = ffma2(q2[2 * i + 1], k0.y, sb);
                sc = ffma2(q2[2 * i + 2], k1.x, sc);
                sd = ffma2(q2[2 * i + 3], k1.y, sd);
            }
            float2 fa = unpack2(sa), fb = unpack2(sb), fc = unpack2(sc), fd = unpack2(sd);
            float s = ((fa.x + fa.y) + (fb.x + fb.y)) + ((fc.x + fc.y) + (fd.x + fd.y));
            s *= SCALE;

            if (s > mmax) {                  // rare after warmup
                ull cd = dup2(__expf(mmax - s));
                l *= unpack2(cd).x;
                #pragma unroll
                for (int i = 0; i < 32; i++) o2[i] = fmul2(o2[i], cd);
                mmax = s;
            }
            float p = __expf(s - mmax);
            l += p;
            ull pd = dup2(p);
            const ulonglong2* vr = (const ulonglong2*)&Vs[j][0];
            #pragma unroll
            for (int i = 0; i < 16; i++) {
                ulonglong2 vv = vr[i];
                o2[2 * i]     = ffma2(pd, vv.x, o2[2 * i]);
                o2[2 * i + 1] = ffma2(pd, vv.y, o2[2 * i + 1]);
            }
        }
    }

    const float inv = 1.f / l;
    float4* op = (float4*)&out[base + (size_t)qrow * H_DIM];
    #pragma unroll
    for (int i = 0; i < 16; i++) {
        float2 a = unpack2(o2[2 * i]);
        float2 c = unpack2(o2[2 * i + 1]);
        op[i] = make_float4(a.x * inv, a.y * inv, c.x * inv, c.y * inv);
    }
}

// ---------------------------------------------------------------------------
extern "C" void kernel_launch(void* const* d_in, const int* in_sizes, int n_in,
                              void* d_out, int out_size)
{
    const float* x  = (const float*)d_in[0];
    const float* Wq = (const float*)d_in[1];
    const float* bq = (const float*)d_in[2];
    const float* Wk = (const float*)d_in[3];
    const float* bk = (const float*)d_in[4];
    const float* Wv = (const float*)d_in[5];
    const float* bv = (const float*)d_in[6];
    float* out = (float*)d_out;

    dim3 ggrid(H_DIM / 64, MROWS / 64, 3);   // (16, 64, 3)
    qkv_gemm_kernel<<<ggrid, 256>>>(x, Wq, bq, Wk, bk, Wv, bv);

    dim3 agrid(SEQ / 64, BATCH * NHEADS);    // (32, 32)
    attn_kernel<<<agrid, 64>>>(out);
}

// round 4
// speedup vs baseline: 1.3548x; 1.3548x over previous
#include <cuda_runtime.h>
#include <cuda_bf16.h>
#include <cstdint>
#include <math.h>

#define H_DIM  1024
#define NHEADS 16
#define HEAD   64
#define BATCH  2
#define SEQ    2048
#define MROWS  (BATCH * SEQ)          // 4096
#define SCALE  0.03125f               // 1/sqrt(1024)
#define K3     3072                   // expanded K (bf16x3)
#define NTOT   3072                   // q|k|v output columns

// ---------------------------------------------------------------------------
// PTX helpers (arch-agnostic: mma.sync / ldmatrix / cp.async only)
// ---------------------------------------------------------------------------
__device__ __forceinline__ uint32_t smem_u32(const void* p) {
    uint32_t a;
    asm("{ .reg .u64 t; cvta.to.shared.u64 t, %1; cvt.u32.u64 %0, t; }" : "=r"(a) : "l"(p));
    return a;
}
__device__ __forceinline__ void cp_async16(uint32_t saddr, const void* gptr) {
    asm volatile("cp.async.cg.shared.global [%0], [%1], 16;" :: "r"(saddr), "l"(gptr) : "memory");
}
#define CP_COMMIT()  asm volatile("cp.async.commit_group;" ::: "memory")
#define CP_WAIT1()   asm volatile("cp.async.wait_group 1;" ::: "memory")

__device__ __forceinline__ void ldmx4(uint32_t* r, uint32_t addr) {
    asm volatile("ldmatrix.sync.aligned.m8n8.x4.shared.b16 {%0,%1,%2,%3}, [%4];"
        : "=r"(r[0]), "=r"(r[1]), "=r"(r[2]), "=r"(r[3]) : "r"(addr));
}
__device__ __forceinline__ void mma16816(float* c, const uint32_t* a, uint32_t b0, uint32_t b1) {
    asm volatile("mma.sync.aligned.m16n8k16.row.col.f32.bf16.bf16.f32 "
        "{%0,%1,%2,%3}, {%4,%5,%6,%7}, {%8,%9}, {%0,%1,%2,%3};"
        : "+f"(c[0]), "+f"(c[1]), "+f"(c[2]), "+f"(c[3])
        : "r"(a[0]), "r"(a[1]), "r"(a[2]), "r"(a[3]), "r"(b0), "r"(b1));
}

// ---------------------------------------------------------------------------
// Device scratch
// ---------------------------------------------------------------------------
__device__ float g_q[MROWS * H_DIM];
__device__ float g_k[MROWS * H_DIM];
__device__ float g_v[MROWS * H_DIM];
__device__ __nv_bfloat16 g_Ax[MROWS * K3];    // [4096, 3072] = [xh | xh | xl]
__device__ __nv_bfloat16 g_Bx[NTOT * K3];     // [3072, 3072] rows n: [wh | wl | wh]

// ---------------------------------------------------------------------------
// Conversion kernels (bf16 hi/lo split)
// ---------------------------------------------------------------------------
__device__ __forceinline__ void split2(float f, __nv_bfloat16& h, __nv_bfloat16& l) {
    h = __float2bfloat16_rn(f);
    l = __float2bfloat16_rn(f - __bfloat162float(h));
}

__global__ __launch_bounds__(256) void convert_x_kernel(const float* __restrict__ x)
{
    int i = blockIdx.x * 256 + threadIdx.x;          // handles 2 consecutive elems
    int m = (2 * i) >> 10;
    int k = (2 * i) & 1023;
    float2 f = *(const float2*)&x[(size_t)2 * i];
    __nv_bfloat162 hh, ll;
    split2(f.x, hh.x, ll.x);
    split2(f.y, hh.y, ll.y);
    __nv_bfloat162* row = (__nv_bfloat162*)&g_Ax[(size_t)m * K3];
    row[(k) >> 1]        = hh;
    row[(k + 1024) >> 1] = hh;
    row[(k + 2048) >> 1] = ll;
}

__global__ __launch_bounds__(256) void convert_w_kernel(
    const float* __restrict__ Wq, const float* __restrict__ Wk, const float* __restrict__ Wv)
{
    int i = blockIdx.x * 256 + threadIdx.x;
    int n = (2 * i) >> 10;
    int k = (2 * i) & 1023;
    const float* W = (n < 1024) ? Wq : (n < 2048) ? Wk : Wv;
    float2 f = *(const float2*)&W[(size_t)(n & 1023) * 1024 + k];
    __nv_bfloat162 hh, ll;
    split2(f.x, hh.x, ll.x);
    split2(f.y, hh.y, ll.y);
    __nv_bfloat162* row = (__nv_bfloat162*)&g_Bx[(size_t)n * K3];
    row[(k) >> 1]        = hh;
    row[(k + 1024) >> 1] = ll;
    row[(k + 2048) >> 1] = hh;
}

// ---------------------------------------------------------------------------
// mma.sync GEMM: C[4096, 3072] = Ax @ Bx^T  (+bias → g_q/g_k/g_v)
// CTA 128x128, 8 warps (4m x 2n), warp tile 32x64, BK=32, cp.async double buf.
// ---------------------------------------------------------------------------
#define BK        32
#define ROWB      40                              // bf16 per smem row (pad 8)
#define BUF_ELE   (128 * ROWB)                    // elems per buffer

__global__ __launch_bounds__(256) void qkv_mma_kernel(
    const float* __restrict__ bq, const float* __restrict__ bk, const float* __restrict__ bv)
{
    __shared__ __nv_bfloat16 Asm[2][BUF_ELE];
    __shared__ __nv_bfloat16 Bsm[2][BUF_ELE];

    const int tid  = threadIdx.x;
    const int wid  = tid >> 5;
    const int lane = tid & 31;
    const int wm   = wid & 3;               // 0..3  (m warp)
    const int wn   = wid >> 2;              // 0..1  (n warp)
    const int m0   = blockIdx.y * 128;
    const int n0   = blockIdx.x * 128;

    const uint32_t sA = smem_u32(Asm);
    const uint32_t sB = smem_u32(Bsm);

    // per-thread cp.async slots: 2 for A, 2 for B per chunk
    const int row_s0 = tid >> 2,          seg_s0 = tid & 3;
    const int row_s1 = (tid + 256) >> 2,  seg_s1 = (tid + 256) & 3;

    #define LOAD_CHUNK(c, buf) do {                                             \
        const __nv_bfloat16* ga0 = &g_Ax[(size_t)(m0 + row_s0) * K3 + (c) * BK + seg_s0 * 8]; \
        const __nv_bfloat16* ga1 = &g_Ax[(size_t)(m0 + row_s1) * K3 + (c) * BK + seg_s1 * 8]; \
        const __nv_bfloat16* gb0 = &g_Bx[(size_t)(n0 + row_s0) * K3 + (c) * BK + seg_s0 * 8]; \
        const __nv_bfloat16* gb1 = &g_Bx[(size_t)(n0 + row_s1) * K3 + (c) * BK + seg_s1 * 8]; \
        cp_async16(sA + (uint32_t)((buf) * BUF_ELE + row_s0 * ROWB + seg_s0 * 8) * 2, ga0);   \
        cp_async16(sA + (uint32_t)((buf) * BUF_ELE + row_s1 * ROWB + seg_s1 * 8) * 2, ga1);   \
        cp_async16(sB + (uint32_t)((buf) * BUF_ELE + row_s0 * ROWB + seg_s0 * 8) * 2, gb0);   \
        cp_async16(sB + (uint32_t)((buf) * BUF_ELE + row_s1 * ROWB + seg_s1 * 8) * 2, gb1);   \
    } while (0)

    float acc[2][8][4];
    #pragma unroll
    for (int mi = 0; mi < 2; mi++)
        #pragma unroll
        for (int nj = 0; nj < 8; nj++)
            #pragma unroll
            for (int t = 0; t < 4; t++) acc[mi][nj][t] = 0.f;

    // ldmatrix lane addressing (offsets within a buffer, in elements)
    const int a_row = wm * 32 + (lane & 15);
    const int a_kof = (lane >> 4) * 8;
    const int b_row_base = wn * 64 + ((lane >> 4) << 3) + (lane & 7);
    const int b_kof = ((lane >> 3) & 1) * 8;

    LOAD_CHUNK(0, 0); CP_COMMIT();
    LOAD_CHUNK(1, 1); CP_COMMIT();

    const int NCH = K3 / BK;   // 96
    for (int c = 0; c < NCH; c++) {
        const int buf = c & 1;
        CP_WAIT1();
        __syncthreads();

        const uint32_t aB = sA + (uint32_t)(buf * BUF_ELE) * 2;
        const uint32_t bB = sB + (uint32_t)(buf * BUF_ELE) * 2;

        #pragma unroll
        for (int ks = 0; ks < 2; ks++) {
            const int k0 = ks * 16;
            uint32_t afr[2][4];
            #pragma unroll
            for (int mi = 0; mi < 2; mi++)
                ldmx4(afr[mi], aB + (uint32_t)((a_row + mi * 16) * ROWB + k0 + a_kof) * 2);
            uint32_t bfr[4][4];
            #pragma unroll
            for (int ni = 0; ni < 4; ni++)
                ldmx4(bfr[ni], bB + (uint32_t)((b_row_base + ni * 16) * ROWB + k0 + b_kof) * 2);
            #pragma unroll
            for (int mi = 0; mi < 2; mi++)
                #pragma unroll
                for (int nj = 0; nj < 8; nj++)
                    mma16816(acc[mi][nj], afr[mi],
                             bfr[nj >> 1][(nj & 1) * 2], bfr[nj >> 1][(nj & 1) * 2 + 1]);
        }

        __syncthreads();
        if (c + 2 < NCH) LOAD_CHUNK(c + 2, buf);
        CP_COMMIT();
    }

    // ---- epilogue: +bias, store to g_q/g_k/g_v ----
    const int which = n0 >> 10;
    float* outm = (which == 0) ? g_q : (which == 1) ? g_k : g_v;
    const float* bias = (which == 0) ? bq : (which == 1) ? bk : bv;
    const int nn0 = n0 & 1023;

    #pragma unroll
    for (int mi = 0; mi < 2; mi++) {
        const int r0 = m0 + wm * 32 + mi * 16 + (lane >> 2);
        #pragma unroll
        for (int nj = 0; nj < 8; nj++) {
            const int col = nn0 + wn * 64 + nj * 8 + (lane & 3) * 2;
            const float2 bb = *(const float2*)&bias[col];
            float2 lo = make_float2(acc[mi][nj][0] + bb.x, acc[mi][nj][1] + bb.y);
            float2 hi = make_float2(acc[mi][nj][2] + bb.x, acc[mi][nj][3] + bb.y);
            *(float2*)&outm[(size_t)r0 * H_DIM + col]       = lo;
            *(float2*)&outm[(size_t)(r0 + 8) * H_DIM + col] = hi;
        }
    }
    #undef LOAD_CHUNK
}

// ---------------------------------------------------------------------------
// Causal attention (R0 scalar version — unchanged)
// ---------------------------------------------------------------------------
__global__ __launch_bounds__(64) void attn_kernel(float* __restrict__ out)
{
    const int qt  = blockIdx.x;
    const int bh  = blockIdx.y;
    const int tid = threadIdx.x;
    const int b   = bh >> 4;
    const int h   = bh & 15;

    const int qrow = qt * 64 + tid;
    const size_t base = ((size_t)(b * SEQ)) * H_DIM + h * HEAD;

    float4 qv[16];
    {
        const float4* qp = (const float4*)&g_q[base + (size_t)qrow * H_DIM];
        #pragma unroll
        for (int i = 0; i < 16; i++) qv[i] = qp[i];
    }

    float4 o4[16];
    #pragma unroll
    for (int i = 0; i < 16; i++) o4[i] = make_float4(0.f, 0.f, 0.f, 0.f);
    float mmax = -1e30f, l = 0.f;

    __shared__ float4 Ks[64][17];
    __shared__ float4 Vs[64][17];

    for (int kt = 0; kt <= qt; kt++) {
        __syncthreads();
        const int krow = kt * 64 + tid;
        const float4* kp = (const float4*)&g_k[base + (size_t)krow * H_DIM];
        const float4* vp = (const float4*)&g_v[base + (size_t)krow * H_DIM];
        #pragma unroll
        for (int i = 0; i < 16; i++) {
            Ks[tid][i] = kp[i];
            Vs[tid][i] = vp[i];
        }
        __syncthreads();

        const int jmax = (kt == qt) ? tid : 63;
        for (int j = 0; j <= jmax; j++) {
            float s0 = 0.f, s1 = 0.f, s2 = 0.f, s3 = 0.f;
            #pragma unroll
            for (int i = 0; i < 16; i++) {
                float4 kv = Ks[j][i];
                s0 += qv[i].x * kv.x;
                s1 += qv[i].y * kv.y;
                s2 += qv[i].z * kv.z;
                s3 += qv[i].w * kv.w;
            }
            float s = ((s0 + s1) + (s2 + s3)) * SCALE;

            if (s > mmax) {
                float cc = __expf(mmax - s);
                l *= cc;
                #pragma unroll
                for (int i = 0; i < 16; i++) {
                    o4[i].x *= cc; o4[i].y *= cc; o4[i].z *= cc; o4[i].w *= cc;
                }
                mmax = s;
            }
            float p = __expf(s - mmax);
            l += p;
            #pragma unroll
            for (int i = 0; i < 16; i++) {
                float4 vv = Vs[j][i];
                o4[i].x += p * vv.x;
                o4[i].y += p * vv.y;
                o4[i].z += p * vv.z;
                o4[i].w += p * vv.w;
            }
        }
    }

    const float inv = 1.f / l;
    float4* op = (float4*)&out[base + (size_t)qrow * H_DIM];
    #pragma unroll
    for (int i = 0; i < 16; i++) {
        float4 r = o4[i];
        r.x *= inv; r.y *= inv; r.z *= inv; r.w *= inv;
        op[i] = r;
    }
}

// ---------------------------------------------------------------------------
extern "C" void kernel_launch(void* const* d_in, const int* in_sizes, int n_in,
                              void* d_out, int out_size)
{
    const float* x  = (const float*)d_in[0];
    const float* Wq = (const float*)d_in[1];
    const float* bq = (const float*)d_in[2];
    const float* Wk = (const float*)d_in[3];
    const float* bk = (const float*)d_in[4];
    const float* Wv = (const float*)d_in[5];
    const float* bv = (const float*)d_in[6];
    float* out = (float*)d_out;

    convert_x_kernel<<<MROWS * H_DIM / 512, 256>>>(x);
    convert_w_kernel<<<NTOT * H_DIM / 512, 256>>>(Wq, Wk, Wv);

    dim3 ggrid(NTOT / 128, MROWS / 128);       // (24, 32)
    qkv_mma_kernel<<<ggrid, 256>>>(bq, bk, bv);

    dim3 agrid(SEQ / 64, BATCH * NHEADS);      // (32, 32)
    attn_kernel<<<agrid, 64>>>(out);
}

// round 5
// speedup vs baseline: 3.7457x; 2.7648x over previous
#include <cuda_runtime.h>
#include <cuda_bf16.h>
#include <cstdint>
#include <math.h>

#define H_DIM  1024
#define NHEADS 16
#define HEAD   64
#define BATCH  2
#define SEQ    2048
#define MROWS  (BATCH * SEQ)          // 4096
#define SCALE  0.03125f               // 1/sqrt(1024)
#define K3     3072                   // expanded K (bf16x3)
#define NTOT   3072                   // q|k|v output columns

// ---------------------------------------------------------------------------
// PTX helpers (arch-agnostic: mma.sync / ldmatrix / cp.async only)
// ---------------------------------------------------------------------------
__device__ __forceinline__ uint32_t smem_u32(const void* p) {
    uint32_t a;
    asm("{ .reg .u64 t; cvta.to.shared.u64 t, %1; cvt.u32.u64 %0, t; }" : "=r"(a) : "l"(p));
    return a;
}
__device__ __forceinline__ void cp_async16(uint32_t saddr, const void* gptr) {
    asm volatile("cp.async.cg.shared.global [%0], [%1], 16;" :: "r"(saddr), "l"(gptr) : "memory");
}
#define CP_COMMIT()  asm volatile("cp.async.commit_group;" ::: "memory")
#define CP_WAIT1()   asm volatile("cp.async.wait_group 1;" ::: "memory")
#define CP_WAIT0()   asm volatile("cp.async.wait_group 0;" ::: "memory")

__device__ __forceinline__ void ldmx4(uint32_t* r, uint32_t addr) {
    asm volatile("ldmatrix.sync.aligned.m8n8.x4.shared.b16 {%0,%1,%2,%3}, [%4];"
        : "=r"(r[0]), "=r"(r[1]), "=r"(r[2]), "=r"(r[3]) : "r"(addr));
}
__device__ __forceinline__ void mma16816(float* c, const uint32_t* a, uint32_t b0, uint32_t b1) {
    asm volatile("mma.sync.aligned.m16n8k16.row.col.f32.bf16.bf16.f32 "
        "{%0,%1,%2,%3}, {%4,%5,%6,%7}, {%8,%9}, {%0,%1,%2,%3};"
        : "+f"(c[0]), "+f"(c[1]), "+f"(c[2]), "+f"(c[3])
        : "r"(a[0]), "r"(a[1]), "r"(a[2]), "r"(a[3]), "r"(b0), "r"(b1));
}

__device__ __forceinline__ void pack_split(float a, float b, uint32_t& hi, uint32_t& lo) {
    __nv_bfloat16 ah = __float2bfloat16_rn(a), bh = __float2bfloat16_rn(b);
    __nv_bfloat162 h; h.x = ah; h.y = bh;
    hi = *(uint32_t*)&h;
    __nv_bfloat162 l;
    l.x = __float2bfloat16_rn(a - __bfloat162float(ah));
    l.y = __float2bfloat16_rn(b - __bfloat162float(bh));
    lo = *(uint32_t*)&l;
}

// ---------------------------------------------------------------------------
// Device scratch
// ---------------------------------------------------------------------------
__device__ float g_v[MROWS * H_DIM];                 // V projection fp32
__device__ __nv_bfloat16 g_qh[MROWS * H_DIM];        // Q bf16 [row, dim]
__device__ __nv_bfloat16 g_kh[MROWS * H_DIM];        // K bf16 [row, dim]
__device__ __nv_bfloat16 g_vth[32 * HEAD * SEQ];     // V^T hi  [bh][dim][key]
__device__ __nv_bfloat16 g_vtl[32 * HEAD * SEQ];     // V^T lo
__device__ __nv_bfloat16 g_Ax[MROWS * K3];           // [4096,3072] = [xh|xh|xl]
__device__ __nv_bfloat16 g_Bx[NTOT * K3];            // rows n: [wh|wl|wh]

// ---------------------------------------------------------------------------
// Conversion kernels (bf16 hi/lo split of x and W)
// ---------------------------------------------------------------------------
__device__ __forceinline__ void split2(float f, __nv_bfloat16& h, __nv_bfloat16& l) {
    h = __float2bfloat16_rn(f);
    l = __float2bfloat16_rn(f - __bfloat162float(h));
}

__global__ __launch_bounds__(256) void convert_x_kernel(const float* __restrict__ x)
{
    int i = blockIdx.x * 256 + threadIdx.x;
    int m = (2 * i) >> 10;
    int k = (2 * i) & 1023;
    float2 f = *(const float2*)&x[(size_t)2 * i];
    __nv_bfloat162 hh, ll;
    split2(f.x, hh.x, ll.x);
    split2(f.y, hh.y, ll.y);
    __nv_bfloat162* row = (__nv_bfloat162*)&g_Ax[(size_t)m * K3];
    row[(k) >> 1]        = hh;
    row[(k + 1024) >> 1] = hh;
    row[(k + 2048) >> 1] = ll;
}

__global__ __launch_bounds__(256) void convert_w_kernel(
    const float* __restrict__ Wq, const float* __restrict__ Wk, const float* __restrict__ Wv)
{
    int i = blockIdx.x * 256 + threadIdx.x;
    int n = (2 * i) >> 10;
    int k = (2 * i) & 1023;
    const float* W = (n < 1024) ? Wq : (n < 2048) ? Wk : Wv;
    float2 f = *(const float2*)&W[(size_t)(n & 1023) * 1024 + k];
    __nv_bfloat162 hh, ll;
    split2(f.x, hh.x, ll.x);
    split2(f.y, hh.y, ll.y);
    __nv_bfloat162* row = (__nv_bfloat162*)&g_Bx[(size_t)n * K3];
    row[(k) >> 1]        = hh;
    row[(k + 1024) >> 1] = ll;
    row[(k + 2048) >> 1] = hh;
}

// ---------------------------------------------------------------------------
// V transpose + hi/lo split:  g_v [b*2048+t][h*64+d] -> g_vth/l [bh][d][t]
// ---------------------------------------------------------------------------
__global__ __launch_bounds__(256) void convert_v_kernel()
{
    __shared__ float vt[128][65];
    const int kc = blockIdx.x;              // 128-key chunk, 0..15
    const int bh = blockIdx.y;              // 0..31
    const int b  = bh >> 4;
    const int h  = bh & 15;
    const int tid = threadIdx.x;

    #pragma unroll
    for (int i = 0; i < 32; i++) {
        int idx = tid + i * 256;            // 8192 = 128 keys x 64 dims
        int key = idx >> 6, d = idx & 63;
        vt[key][d] = g_v[(size_t)(b * SEQ + kc * 128 + key) * H_DIM + h * HEAD + d];
    }
    __syncthreads();
    #pragma unroll
    for (int i = 0; i < 32; i++) {
        int idx = tid + i * 256;
        int d = idx >> 7, key = idx & 127;
        float f = vt[key][d];
        __nv_bfloat16 hh = __float2bfloat16_rn(f);
        __nv_bfloat16 ll = __float2bfloat16_rn(f - __bfloat162float(hh));
        size_t o = ((size_t)bh * HEAD + d) * SEQ + kc * 128 + key;
        g_vth[o] = hh;
        g_vtl[o] = ll;
    }
}

// ---------------------------------------------------------------------------
// mma.sync GEMM: C[4096, 3072] = Ax @ Bx^T  (+bias → g_qh/g_kh bf16, g_v fp32)
// ---------------------------------------------------------------------------
#define BK        32
#define ROWB      40
#define BUF_ELE   (128 * ROWB)

__global__ __launch_bounds__(256) void qkv_mma_kernel(
    const float* __restrict__ bq, const float* __restrict__ bk, const float* __restrict__ bv)
{
    __shared__ __nv_bfloat16 Asm[2][BUF_ELE];
    __shared__ __nv_bfloat16 Bsm[2][BUF_ELE];

    const int tid  = threadIdx.x;
    const int wid  = tid >> 5;
    const int lane = tid & 31;
    const int wm   = wid & 3;
    const int wn   = wid >> 2;
    const int m0   = blockIdx.y * 128;
    const int n0   = blockIdx.x * 128;

    const uint32_t sA = smem_u32(Asm);
    const uint32_t sB = smem_u32(Bsm);

    const int row_s0 = tid >> 2,          seg_s0 = tid & 3;
    const int row_s1 = (tid + 256) >> 2,  seg_s1 = (tid + 256) & 3;

    #define LOAD_CHUNK(c, buf) do {                                             \
        const __nv_bfloat16* ga0 = &g_Ax[(size_t)(m0 + row_s0) * K3 + (c) * BK + seg_s0 * 8]; \
        const __nv_bfloat16* ga1 = &g_Ax[(size_t)(m0 + row_s1) * K3 + (c) * BK + seg_s1 * 8]; \
        const __nv_bfloat16* gb0 = &g_Bx[(size_t)(n0 + row_s0) * K3 + (c) * BK + seg_s0 * 8]; \
        const __nv_bfloat16* gb1 = &g_Bx[(size_t)(n0 + row_s1) * K3 + (c) * BK + seg_s1 * 8]; \
        cp_async16(sA + (uint32_t)((buf) * BUF_ELE + row_s0 * ROWB + seg_s0 * 8) * 2, ga0);   \
        cp_async16(sA + (uint32_t)((buf) * BUF_ELE + row_s1 * ROWB + seg_s1 * 8) * 2, ga1);   \
        cp_async16(sB + (uint32_t)((buf) * BUF_ELE + row_s0 * ROWB + seg_s0 * 8) * 2, gb0);   \
        cp_async16(sB + (uint32_t)((buf) * BUF_ELE + row_s1 * ROWB + seg_s1 * 8) * 2, gb1);   \
    } while (0)

    float acc[2][8][4];
    #pragma unroll
    for (int mi = 0; mi < 2; mi++)
        #pragma unroll
        for (int nj = 0; nj < 8; nj++)
            #pragma unroll
            for (int t = 0; t < 4; t++) acc[mi][nj][t] = 0.f;

    const int a_row = wm * 32 + (lane & 15);
    const int a_kof = (lane >> 4) * 8;
    const int b_row_base = wn * 64 + ((lane >> 4) << 3) + (lane & 7);
    const int b_kof = ((lane >> 3) & 1) * 8;

    LOAD_CHUNK(0, 0); CP_COMMIT();
    LOAD_CHUNK(1, 1); CP_COMMIT();

    const int NCH = K3 / BK;   // 96
    for (int c = 0; c < NCH; c++) {
        const int buf = c & 1;
        CP_WAIT1();
        __syncthreads();

        const uint32_t aB = sA + (uint32_t)(buf * BUF_ELE) * 2;
        const uint32_t bB = sB + (uint32_t)(buf * BUF_ELE) * 2;

        #pragma unroll
        for (int ks = 0; ks < 2; ks++) {
            const int k0 = ks * 16;
            uint32_t afr[2][4];
            #pragma unroll
            for (int mi = 0; mi < 2; mi++)
                ldmx4(afr[mi], aB + (uint32_t)((a_row + mi * 16) * ROWB + k0 + a_kof) * 2);
            uint32_t bfr[4][4];
            #pragma unroll
            for (int ni = 0; ni < 4; ni++)
                ldmx4(bfr[ni], bB + (uint32_t)((b_row_base + ni * 16) * ROWB + k0 + b_kof) * 2);
            #pragma unroll
            for (int mi = 0; mi < 2; mi++)
                #pragma unroll
                for (int nj = 0; nj < 8; nj++)
                    mma16816(acc[mi][nj], afr[mi],
                             bfr[nj >> 1][(nj & 1) * 2], bfr[nj >> 1][(nj & 1) * 2 + 1]);
        }

        __syncthreads();
        if (c + 2 < NCH) LOAD_CHUNK(c + 2, buf);
        CP_COMMIT();
    }

    // ---- epilogue ----
    const int which = n0 >> 10;
    const float* bias = (which == 0) ? bq : (which == 1) ? bk : bv;
    const int nn0 = n0 & 1023;

    #pragma unroll
    for (int mi = 0; mi < 2; mi++) {
        const int r0 = m0 + wm * 32 + mi * 16 + (lane >> 2);
        #pragma unroll
        for (int nj = 0; nj < 8; nj++) {
            const int col = nn0 + wn * 64 + nj * 8 + (lane & 3) * 2;
            const float2 bb = *(const float2*)&bias[col];
            float lox = acc[mi][nj][0] + bb.x, loy = acc[mi][nj][1] + bb.y;
            float hix = acc[mi][nj][2] + bb.x, hiy = acc[mi][nj][3] + bb.y;
            if (which == 2) {
                *(float2*)&g_v[(size_t)r0 * H_DIM + col]       = make_float2(lox, loy);
                *(float2*)&g_v[(size_t)(r0 + 8) * H_DIM + col] = make_float2(hix, hiy);
            } else {
                __nv_bfloat16* ob = (which == 0) ? g_qh : g_kh;
                __nv_bfloat162 plo; plo.x = __float2bfloat16_rn(lox); plo.y = __float2bfloat16_rn(loy);
                __nv_bfloat162 phi; phi.x = __float2bfloat16_rn(hix); phi.y = __float2bfloat16_rn(hiy);
                *(__nv_bfloat162*)&ob[(size_t)r0 * H_DIM + col]       = plo;
                *(__nv_bfloat162*)&ob[(size_t)(r0 + 8) * H_DIM + col] = phi;
            }
        }
    }
    #undef LOAD_CHUNK
}

// ---------------------------------------------------------------------------
// FlashAttention-2 style causal attention with mma.sync.
// CTA: 128 q-rows x one (b,h). 8 warps, each owns a 16-row stripe.
// K tiles of 64 keys; Vh/Vl staged transposed [dim][key].
// ---------------------------------------------------------------------------
#define FROWB    72
#define QS_OFF   0
#define QS_BYTES (128 * FROWB * 2)                 // 18432
#define KS_OFF   QS_BYTES
#define KV_BUF   (64 * FROWB * 2)                  // 9216
#define VH_OFF   (KS_OFF + 2 * KV_BUF)
#define VL_OFF   (VH_OFF + 2 * KV_BUF)
#define ATTN_SMEM (VL_OFF + 2 * KV_BUF)            // 73728

__global__ __launch_bounds__(256) void fattn_kernel(float* __restrict__ out)
{
    extern __shared__ char sm[];
    const uint32_t sQ = smem_u32(sm) + QS_OFF;
    const uint32_t sK = smem_u32(sm) + KS_OFF;
    const uint32_t sVh = smem_u32(sm) + VH_OFF;
    const uint32_t sVl = smem_u32(sm) + VL_OFF;

    const int qt  = (gridDim.x - 1) - blockIdx.x;   // heavy tiles first
    const int bh  = blockIdx.y;
    const int b   = bh >> 4;
    const int h   = bh & 15;
    const int q0  = qt * 128;
    const int tid = threadIdx.x;
    const int wid = tid >> 5;
    const int lane = tid & 31;

    // ---- Q tile loads (bf16, 128 rows x 64 dims) ----
    #pragma unroll
    for (int i = 0; i < 4; i++) {
        int id = tid + i * 256; int row = id >> 3; int seg = id & 7;
        cp_async16(sQ + (uint32_t)(row * FROWB + seg * 8) * 2,
                   &g_qh[(size_t)(b * SEQ + q0 + row) * H_DIM + h * HEAD + seg * 8]);
    }
    CP_COMMIT();

    #define LOAD_KV(kt_, buf_) do {                                            \
        const int k0_ = (kt_) * 64;                                            \
        _Pragma("unroll")                                                      \
        for (int i = 0; i < 2; i++) {                                          \
            int id = tid + i * 256; int row = id >> 3; int seg = id & 7;       \
            cp_async16(sK + (uint32_t)((buf_) * (64 * FROWB) + row * FROWB + seg * 8) * 2, \
                &g_kh[(size_t)(b * SEQ + k0_ + row) * H_DIM + h * HEAD + seg * 8]); \
            cp_async16(sVh + (uint32_t)((buf_) * (64 * FROWB) + row * FROWB + seg * 8) * 2, \
                &g_vth[((size_t)bh * HEAD + row) * SEQ + k0_ + seg * 8]);      \
            cp_async16(sVl + (uint32_t)((buf_) * (64 * FROWB) + row * FROWB + seg * 8) * 2, \
                &g_vtl[((size_t)bh * HEAD + row) * SEQ + k0_ + seg * 8]);      \
        }                                                                      \
    } while (0)

    LOAD_KV(0, 0);
    CP_COMMIT();

    // ---- wait Q, build Q A-frags ----
    CP_WAIT1();
    __syncthreads();
    uint32_t qf[4][4];
    {
        const int a_row = wid * 16 + (lane & 15);
        const int a_kof = (lane >> 4) * 8;
        #pragma unroll
        for (int t = 0; t < 4; t++)
            ldmx4(qf[t], sQ + (uint32_t)(a_row * FROWB + t * 16 + a_kof) * 2);
    }

    float O[8][4];
    #pragma unroll
    for (int j = 0; j < 8; j++)
        #pragma unroll
        for (int t = 0; t < 4; t++) O[j][t] = 0.f;
    float m_lo = -1e30f, m_hi = -1e30f, l_lo = 0.f, l_hi = 0.f;

    const int r_lo = q0 + wid * 16 + (lane >> 2);
    const int b_nrow = ((lane >> 4) << 3) + (lane & 7);
    const int b_kof  = ((lane >> 3) & 1) * 8;

    const int nt = 2 * qt + 2;
    for (int kt = 0; kt < nt; kt++) {
        const int buf = kt & 1;
        CP_WAIT0();
        __syncthreads();
        if (kt + 1 < nt) LOAD_KV(kt + 1, buf ^ 1);
        CP_COMMIT();

        const uint32_t kB  = sK  + (uint32_t)(buf * 64 * FROWB) * 2;
        const uint32_t vhB = sVh + (uint32_t)(buf * 64 * FROWB) * 2;
        const uint32_t vlB = sVl + (uint32_t)(buf * 64 * FROWB) * 2;

        // ---- S = Q K^T (scaled later) ----
        float c[8][4];
        #pragma unroll
        for (int j = 0; j < 8; j++)
            #pragma unroll
            for (int t = 0; t < 4; t++) c[j][t] = 0.f;

        #pragma unroll
        for (int t = 0; t < 4; t++) {
            uint32_t kf[4][4];
            #pragma unroll
            for (int ng = 0; ng < 4; ng++)
                ldmx4(kf[ng], kB + (uint32_t)((ng * 16 + b_nrow) * FROWB + t * 16 + b_kof) * 2);
            #pragma unroll
            for (int nj = 0; nj < 8; nj++)
                mma16816(c[nj], qf[t], kf[nj >> 1][(nj & 1) * 2], kf[nj >> 1][(nj & 1) * 2 + 1]);
        }

        #pragma unroll
        for (int j = 0; j < 8; j++) {
            c[j][0] *= SCALE; c[j][1] *= SCALE; c[j][2] *= SCALE; c[j][3] *= SCALE;
        }

        // ---- causal mask (only diagonal tiles) ----
        if (kt >= 2 * qt) {
            const int col0 = kt * 64 + (lane & 3) * 2;
            #pragma unroll
            for (int j = 0; j < 8; j++) {
                const int cc = col0 + j * 8;
                if (cc     > r_lo)     c[j][0] = -1e30f;
                if (cc + 1 > r_lo)     c[j][1] = -1e30f;
                if (cc     > r_lo + 8) c[j][2] = -1e30f;
                if (cc + 1 > r_lo + 8) c[j][3] = -1e30f;
            }
        }

        // ---- online softmax ----
        float tmax_lo = c[0][0], tmax_hi = c[0][2];
        #pragma unroll
        for (int j = 0; j < 8; j++) {
            tmax_lo = fmaxf(tmax_lo, fmaxf(c[j][0], c[j][1]));
            tmax_hi = fmaxf(tmax_hi, fmaxf(c[j][2], c[j][3]));
        }
        tmax_lo = fmaxf(tmax_lo, __shfl_xor_sync(0xffffffffu, tmax_lo, 1));
        tmax_lo = fmaxf(tmax_lo, __shfl_xor_sync(0xffffffffu, tmax_lo, 2));
        tmax_hi = fmaxf(tmax_hi, __shfl_xor_sync(0xffffffffu, tmax_hi, 1));
        tmax_hi = fmaxf(tmax_hi, __shfl_xor_sync(0xffffffffu, tmax_hi, 2));

        const float mn_lo = fmaxf(m_lo, tmax_lo);
        const float mn_hi = fmaxf(m_hi, tmax_hi);
        const float sc_lo = __expf(m_lo - mn_lo);
        const float sc_hi = __expf(m_hi - mn_hi);
        m_lo = mn_lo; m_hi = mn_hi;

        float sum_lo = 0.f, sum_hi = 0.f;
        #pragma unroll
        for (int j = 0; j < 8; j++) {
            c[j][0] = __expf(c[j][0] - mn_lo);
            c[j][1] = __expf(c[j][1] - mn_lo);
            c[j][2] = __expf(c[j][2] - mn_hi);
            c[j][3] = __expf(c[j][3] - mn_hi);
            sum_lo += c[j][0] + c[j][1];
            sum_hi += c[j][2] + c[j][3];
        }
        sum_lo += __shfl_xor_sync(0xffffffffu, sum_lo, 1);
        sum_lo += __shfl_xor_sync(0xffffffffu, sum_lo, 2);
        sum_hi += __shfl_xor_sync(0xffffffffu, sum_hi, 1);
        sum_hi += __shfl_xor_sync(0xffffffffu, sum_hi, 2);
        l_lo = l_lo * sc_lo + sum_lo;
        l_hi = l_hi * sc_hi + sum_hi;

        #pragma unroll
        for (int j = 0; j < 8; j++) {
            O[j][0] *= sc_lo; O[j][1] *= sc_lo; O[j][2] *= sc_hi; O[j][3] *= sc_hi;
        }

        // ---- pack P hi/lo A-frags (C-frag layout == A-frag layout) ----
        uint32_t ph[4][4], pl[4][4];
        #pragma unroll
        for (int t = 0; t < 4; t++) {
            const int j0 = 2 * t, j1 = 2 * t + 1;
            pack_split(c[j0][0], c[j0][1], ph[t][0], pl[t][0]);
            pack_split(c[j0][2], c[j0][3], ph[t][1], pl[t][1]);
            pack_split(c[j1][0], c[j1][1], ph[t][2], pl[t][2]);
            pack_split(c[j1][2], c[j1][3], ph[t][3], pl[t][3]);
        }

        // ---- O += ph*Vh + ph*Vl + pl*Vh ----
        #pragma unroll
        for (int t = 0; t < 4; t++) {
            uint32_t vbh[4][4], vbl[4][4];
            #pragma unroll
            for (int ng = 0; ng < 4; ng++) {
                ldmx4(vbh[ng], vhB + (uint32_t)((ng * 16 + b_nrow) * FROWB + t * 16 + b_kof) * 2);
                ldmx4(vbl[ng], vlB + (uint32_t)((ng * 16 + b_nrow) * FROWB + t * 16 + b_kof) * 2);
            }
            #pragma unroll
            for (int nj = 0; nj < 8; nj++) {
                const uint32_t bh0 = vbh[nj >> 1][(nj & 1) * 2], bh1 = vbh[nj >> 1][(nj & 1) * 2 + 1];
                const uint32_t bl0 = vbl[nj >> 1][(nj & 1) * 2], bl1 = vbl[nj >> 1][(nj & 1) * 2 + 1];
                mma16816(O[nj], ph[t], bh0, bh1);
                mma16816(O[nj], ph[t], bl0, bl1);
                mma16816(O[nj], pl[t], bh0, bh1);
            }
        }
    }

    // ---- epilogue ----
    const float inv_lo = 1.f / l_lo;
    const float inv_hi = 1.f / l_hi;
    #pragma unroll
    for (int j = 0; j < 8; j++) {
        const int col = h * HEAD + j * 8 + (lane & 3) * 2;
        *(float2*)&out[(size_t)(b * SEQ + r_lo) * H_DIM + col] =
            make_float2(O[j][0] * inv_lo, O[j][1] * inv_lo);
        *(float2*)&out[(size_t)(b * SEQ + r_lo + 8) * H_DIM + col] =
            make_float2(O[j][2] * inv_hi, O[j][3] * inv_hi);
    }
    #undef LOAD_KV
}

// ---------------------------------------------------------------------------
extern "C" void kernel_launch(void* const* d_in, const int* in_sizes, int n_in,
                              void* d_out, int out_size)
{
    const float* x  = (const float*)d_in[0];
    const float* Wq = (const float*)d_in[1];
    const float* bq = (const float*)d_in[2];
    const float* Wk = (const float*)d_in[3];
    const float* bk = (const float*)d_in[4];
    const float* Wv = (const float*)d_in[5];
    const float* bv = (const float*)d_in[6];
    float* out = (float*)d_out;

    cudaFuncSetAttribute(fattn_kernel,
                         cudaFuncAttributeMaxDynamicSharedMemorySize, ATTN_SMEM);

    convert_x_kernel<<<MROWS * H_DIM / 512, 256>>>(x);
    convert_w_kernel<<<NTOT * H_DIM / 512, 256>>>(Wq, Wk, Wv);

    dim3 ggrid(NTOT / 128, MROWS / 128);       // (24, 32)
    qkv_mma_kernel<<<ggrid, 256>>>(bq, bk, bv);

    dim3 vgrid(SEQ / 128, 32);                 // (16, 32)
    convert_v_kernel<<<vgrid, 256>>>();

    dim3 agrid(SEQ / 128, BATCH * NHEADS);     // (16, 32)
    fattn_kernel<<<agrid, 256, ATTN_SMEM>>>(out);
}

// round 6
// speedup vs baseline: 4.7345x; 1.2640x over previous
#include <cuda_runtime.h>
#include <cuda_bf16.h>
#include <cstdint>
#include <math.h>

#define H_DIM  1024
#define NHEADS 16
#define HEAD   64
#define BATCH  2
#define SEQ    2048
#define MROWS  (BATCH * SEQ)          // 4096
#define SCALE  0.03125f               // 1/sqrt(1024)
#define K2     2048                   // [hi | lo] expanded K
#define NTOT   3072                   // q|k|v output columns

// ---------------------------------------------------------------------------
// PTX helpers (arch-agnostic: mma.sync / ldmatrix / cp.async only)
// ---------------------------------------------------------------------------
__device__ __forceinline__ uint32_t smem_u32(const void* p) {
    uint32_t a;
    asm("{ .reg .u64 t; cvta.to.shared.u64 t, %1; cvt.u32.u64 %0, t; }" : "=r"(a) : "l"(p));
    return a;
}
__device__ __forceinline__ void cp_async16(uint32_t saddr, const void* gptr) {
    asm volatile("cp.async.cg.shared.global [%0], [%1], 16;" :: "r"(saddr), "l"(gptr) : "memory");
}
#define CP_COMMIT()  asm volatile("cp.async.commit_group;" ::: "memory")
#define CP_WAIT1()   asm volatile("cp.async.wait_group 1;" ::: "memory")
#define CP_WAIT0()   asm volatile("cp.async.wait_group 0;" ::: "memory")

__device__ __forceinline__ void ldmx4(uint32_t* r, uint32_t addr) {
    asm volatile("ldmatrix.sync.aligned.m8n8.x4.shared.b16 {%0,%1,%2,%3}, [%4];"
        : "=r"(r[0]), "=r"(r[1]), "=r"(r[2]), "=r"(r[3]) : "r"(addr));
}
__device__ __forceinline__ void mma16816(float* c, const uint32_t* a, uint32_t b0, uint32_t b1) {
    asm volatile("mma.sync.aligned.m16n8k16.row.col.f32.bf16.bf16.f32 "
        "{%0,%1,%2,%3}, {%4,%5,%6,%7}, {%8,%9}, {%0,%1,%2,%3};"
        : "+f"(c[0]), "+f"(c[1]), "+f"(c[2]), "+f"(c[3])
        : "r"(a[0]), "r"(a[1]), "r"(a[2]), "r"(a[3]), "r"(b0), "r"(b1));
}

__device__ __forceinline__ void pack_split(float a, float b, uint32_t& hi, uint32_t& lo) {
    __nv_bfloat16 ah = __float2bfloat16_rn(a), bh = __float2bfloat16_rn(b);
    __nv_bfloat162 h; h.x = ah; h.y = bh;
    hi = *(uint32_t*)&h;
    __nv_bfloat162 l;
    l.x = __float2bfloat16_rn(a - __bfloat162float(ah));
    l.y = __float2bfloat16_rn(b - __bfloat162float(bh));
    lo = *(uint32_t*)&l;
}

// ---------------------------------------------------------------------------
// Device scratch
// ---------------------------------------------------------------------------
__device__ float g_v[MROWS * H_DIM];                 // V projection fp32
__device__ __nv_bfloat16 g_qh[MROWS * H_DIM];        // Q bf16 [row, dim]
__device__ __nv_bfloat16 g_kh[MROWS * H_DIM];        // K bf16 [row, dim]
__device__ __nv_bfloat16 g_vth[32 * HEAD * SEQ];     // V^T hi  [bh][dim][key]
__device__ __nv_bfloat16 g_vtl[32 * HEAD * SEQ];     // V^T lo
__device__ __nv_bfloat16 g_Ax[MROWS * K2];           // [4096,2048] = [xh | xl]
__device__ __nv_bfloat16 g_Bx[NTOT * K2];            // rows n: [wh | wl]

// ---------------------------------------------------------------------------
// Conversion kernels (bf16 hi/lo split of x and W)
// ---------------------------------------------------------------------------
__device__ __forceinline__ void split2(float f, __nv_bfloat16& h, __nv_bfloat16& l) {
    h = __float2bfloat16_rn(f);
    l = __float2bfloat16_rn(f - __bfloat162float(h));
}

__global__ __launch_bounds__(256) void convert_x_kernel(const float* __restrict__ x)
{
    int i = blockIdx.x * 256 + threadIdx.x;
    int m = (2 * i) >> 10;
    int k = (2 * i) & 1023;
    float2 f = *(const float2*)&x[(size_t)2 * i];
    __nv_bfloat162 hh, ll;
    split2(f.x, hh.x, ll.x);
    split2(f.y, hh.y, ll.y);
    __nv_bfloat162* row = (__nv_bfloat162*)&g_Ax[(size_t)m * K2];
    row[(k) >> 1]        = hh;
    row[(k + 1024) >> 1] = ll;
}

__global__ __launch_bounds__(256) void convert_w_kernel(
    const float* __restrict__ Wq, const float* __restrict__ Wk, const float* __restrict__ Wv)
{
    int i = blockIdx.x * 256 + threadIdx.x;
    int n = (2 * i) >> 10;
    int k = (2 * i) & 1023;
    const float* W = (n < 1024) ? Wq : (n < 2048) ? Wk : Wv;
    float2 f = *(const float2*)&W[(size_t)(n & 1023) * 1024 + k];
    __nv_bfloat162 hh, ll;
    split2(f.x, hh.x, ll.x);
    split2(f.y, hh.y, ll.y);
    __nv_bfloat162* row = (__nv_bfloat162*)&g_Bx[(size_t)n * K2];
    row[(k) >> 1]        = hh;
    row[(k + 1024) >> 1] = ll;
}

// ---------------------------------------------------------------------------
// V transpose + hi/lo split:  g_v [b*2048+t][h*64+d] -> g_vth/l [bh][d][t]
// ---------------------------------------------------------------------------
__global__ __launch_bounds__(256) void convert_v_kernel()
{
    __shared__ float vt[128][65];
    const int kc = blockIdx.x;              // 128-key chunk, 0..15
    const int bh = blockIdx.y;              // 0..31
    const int b  = bh >> 4;
    const int h  = bh & 15;
    const int tid = threadIdx.x;

    #pragma unroll
    for (int i = 0; i < 32; i++) {
        int idx = tid + i * 256;            // 8192 = 128 keys x 64 dims
        int key = idx >> 6, d = idx & 63;
        vt[key][d] = g_v[(size_t)(b * SEQ + kc * 128 + key) * H_DIM + h * HEAD + d];
    }
    __syncthreads();
    #pragma unroll
    for (int i = 0; i < 32; i++) {
        int idx = tid + i * 256;
        int d = idx >> 7, key = idx & 127;
        float f = vt[key][d];
        __nv_bfloat16 hh = __float2bfloat16_rn(f);
        __nv_bfloat16 ll = __float2bfloat16_rn(f - __bfloat162float(hh));
        size_t o = ((size_t)bh * HEAD + d) * SEQ + kc * 128 + key;
        g_vth[o] = hh;
        g_vtl[o] = ll;
    }
}

// ---------------------------------------------------------------------------
// mma.sync GEMM:
//   Q/K tiles (n0 < 2048): single term  xh·wh^T            (32 K-chunks)
//   V tiles   (n0 >= 2048): xh·wh + xh·wl + xl·wh          (96 K-chunks)
// Chunk c → term t = c>>5: A-col-offset {0,0,1024}, B-col-offset {0,1024,0}.
// ---------------------------------------------------------------------------
#define BK        32
#define ROWB      40
#define BUF_ELE   (128 * ROWB)

__global__ __launch_bounds__(256) void qkv_mma_kernel(
    const float* __restrict__ bq, const float* __restrict__ bk, const float* __restrict__ bv)
{
    __shared__ __nv_bfloat16 Asm[2][BUF_ELE];
    __shared__ __nv_bfloat16 Bsm[2][BUF_ELE];

    const int tid  = threadIdx.x;
    const int wid  = tid >> 5;
    const int lane = tid & 31;
    const int wm   = wid & 3;
    const int wn   = wid >> 2;
    const int m0   = blockIdx.y * 128;
    const int n0   = blockIdx.x * 128;
    const int which = n0 >> 10;

    const uint32_t sA = smem_u32(Asm);
    const uint32_t sB = smem_u32(Bsm);

    const int row_s0 = tid >> 2,          seg_s0 = tid & 3;
    const int row_s1 = (tid + 256) >> 2,  seg_s1 = (tid + 256) & 3;

    #define LOAD_CHUNK(c, buf) do {                                             \
        const int t_   = (c) >> 5;                                              \
        const int kin_ = ((c) & 31) * BK;                                       \
        const int ao_  = (t_ == 2) ? 1024 : 0;                                  \
        const int bo_  = (t_ == 1) ? 1024 : 0;                                  \
        const __nv_bfloat16* ga0 = &g_Ax[(size_t)(m0 + row_s0) * K2 + ao_ + kin_ + seg_s0 * 8]; \
        const __nv_bfloat16* ga1 = &g_Ax[(size_t)(m0 + row_s1) * K2 + ao_ + kin_ + seg_s1 * 8]; \
        const __nv_bfloat16* gb0 = &g_Bx[(size_t)(n0 + row_s0) * K2 + bo_ + kin_ + seg_s0 * 8]; \
        const __nv_bfloat16* gb1 = &g_Bx[(size_t)(n0 + row_s1) * K2 + bo_ + kin_ + seg_s1 * 8]; \
        cp_async16(sA + (uint32_t)((buf) * BUF_ELE + row_s0 * ROWB + seg_s0 * 8) * 2, ga0);   \
        cp_async16(sA + (uint32_t)((buf) * BUF_ELE + row_s1 * ROWB + seg_s1 * 8) * 2, ga1);   \
        cp_async16(sB + (uint32_t)((buf) * BUF_ELE + row_s0 * ROWB + seg_s0 * 8) * 2, gb0);   \
        cp_async16(sB + (uint32_t)((buf) * BUF_ELE + row_s1 * ROWB + seg_s1 * 8) * 2, gb1);   \
    } while (0)

    float acc[2][8][4];
    #pragma unroll
    for (int mi = 0; mi < 2; mi++)
        #pragma unroll
        for (int nj = 0; nj < 8; nj++)
            #pragma unroll
            for (int t = 0; t < 4; t++) acc[mi][nj][t] = 0.f;

    const int a_row = wm * 32 + (lane & 15);
    const int a_kof = (lane >> 4) * 8;
    const int b_row_base = wn * 64 + ((lane >> 4) << 3) + (lane & 7);
    const int b_kof = ((lane >> 3) & 1) * 8;

    LOAD_CHUNK(0, 0); CP_COMMIT();
    LOAD_CHUNK(1, 1); CP_COMMIT();

    const int NCH = (which == 2) ? 96 : 32;   // V: 3 terms, Q/K: 1 term
    for (int c = 0; c < NCH; c++) {
        const int buf = c & 1;
        CP_WAIT1();
        __syncthreads();

        const uint32_t aB = sA + (uint32_t)(buf * BUF_ELE) * 2;
        const uint32_t bB = sB + (uint32_t)(buf * BUF_ELE) * 2;

        #pragma unroll
        for (int ks = 0; ks < 2; ks++) {
            const int k0 = ks * 16;
            uint32_t afr[2][4];
            #pragma unroll
            for (int mi = 0; mi < 2; mi++)
                ldmx4(afr[mi], aB + (uint32_t)((a_row + mi * 16) * ROWB + k0 + a_kof) * 2);
            uint32_t bfr[4][4];
            #pragma unroll
            for (int ni = 0; ni < 4; ni++)
                ldmx4(bfr[ni], bB + (uint32_t)((b_row_base + ni * 16) * ROWB + k0 + b_kof) * 2);
            #pragma unroll
            for (int mi = 0; mi < 2; mi++)
                #pragma unroll
                for (int nj = 0; nj < 8; nj++)
                    mma16816(acc[mi][nj], afr[mi],
                             bfr[nj >> 1][(nj & 1) * 2], bfr[nj >> 1][(nj & 1) * 2 + 1]);
        }

        __syncthreads();
        if (c + 2 < NCH) LOAD_CHUNK(c + 2, buf);
        CP_COMMIT();
    }

    // ---- epilogue ----
    const float* bias = (which == 0) ? bq : (which == 1) ? bk : bv;
    const int nn0 = n0 & 1023;

    #pragma unroll
    for (int mi = 0; mi < 2; mi++) {
        const int r0 = m0 + wm * 32 + mi * 16 + (lane >> 2);
        #pragma unroll
        for (int nj = 0; nj < 8; nj++) {
            const int col = nn0 + wn * 64 + nj * 8 + (lane & 3) * 2;
            const float2 bb = *(const float2*)&bias[col];
            float lox = acc[mi][nj][0] + bb.x, loy = acc[mi][nj][1] + bb.y;
            float hix = acc[mi][nj][2] + bb.x, hiy = acc[mi][nj][3] + bb.y;
            if (which == 2) {
                *(float2*)&g_v[(size_t)r0 * H_DIM + col]       = make_float2(lox, loy);
                *(float2*)&g_v[(size_t)(r0 + 8) * H_DIM + col] = make_float2(hix, hiy);
            } else {
                __nv_bfloat16* ob = (which == 0) ? g_qh : g_kh;
                __nv_bfloat162 plo; plo.x = __float2bfloat16_rn(lox); plo.y = __float2bfloat16_rn(loy);
                __nv_bfloat162 phi; phi.x = __float2bfloat16_rn(hix); phi.y = __float2bfloat16_rn(hiy);
                *(__nv_bfloat162*)&ob[(size_t)r0 * H_DIM + col]       = plo;
                *(__nv_bfloat162*)&ob[(size_t)(r0 + 8) * H_DIM + col] = phi;
            }
        }
    }
    #undef LOAD_CHUNK
}

// ---------------------------------------------------------------------------
// FlashAttention-2 style causal attention with mma.sync (unchanged from R4).
// ---------------------------------------------------------------------------
#define FROWB    72
#define QS_OFF   0
#define QS_BYTES (128 * FROWB * 2)                 // 18432
#define KS_OFF   QS_BYTES
#define KV_BUF   (64 * FROWB * 2)                  // 9216
#define VH_OFF   (KS_OFF + 2 * KV_BUF)
#define VL_OFF   (VH_OFF + 2 * KV_BUF)
#define ATTN_SMEM (VL_OFF + 2 * KV_BUF)            // 73728

__global__ __launch_bounds__(256) void fattn_kernel(float* __restrict__ out)
{
    extern __shared__ char sm[];
    const uint32_t sQ = smem_u32(sm) + QS_OFF;
    const uint32_t sK = smem_u32(sm) + KS_OFF;
    const uint32_t sVh = smem_u32(sm) + VH_OFF;
    const uint32_t sVl = smem_u32(sm) + VL_OFF;

    const int qt  = (gridDim.x - 1) - blockIdx.x;   // heavy tiles first
    const int bh  = blockIdx.y;
    const int b   = bh >> 4;
    const int h   = bh & 15;
    const int q0  = qt * 128;
    const int tid = threadIdx.x;
    const int wid = tid >> 5;
    const int lane = tid & 31;

    #pragma unroll
    for (int i = 0; i < 4; i++) {
        int id = tid + i * 256; int row = id >> 3; int seg = id & 7;
        cp_async16(sQ + (uint32_t)(row * FROWB + seg * 8) * 2,
                   &g_qh[(size_t)(b * SEQ + q0 + row) * H_DIM + h * HEAD + seg * 8]);
    }
    CP_COMMIT();

    #define LOAD_KV(kt_, buf_) do {                                            \
        const int k0_ = (kt_) * 64;                                            \
        _Pragma("unroll")                                                      \
        for (int i = 0; i < 2; i++) {                                          \
            int id = tid + i * 256; int row = id >> 3; int seg = id & 7;       \
            cp_async16(sK + (uint32_t)((buf_) * (64 * FROWB) + row * FROWB + seg * 8) * 2, \
                &g_kh[(size_t)(b * SEQ + k0_ + row) * H_DIM + h * HEAD + seg * 8]); \
            cp_async16(sVh + (uint32_t)((buf_) * (64 * FROWB) + row * FROWB + seg * 8) * 2, \
                &g_vth[((size_t)bh * HEAD + row) * SEQ + k0_ + seg * 8]);      \
            cp_async16(sVl + (uint32_t)((buf_) * (64 * FROWB) + row * FROWB + seg * 8) * 2, \
                &g_vtl[((size_t)bh * HEAD + row) * SEQ + k0_ + seg * 8]);      \
        }                                                                      \
    } while (0)

    LOAD_KV(0, 0);
    CP_COMMIT();

    CP_WAIT1();
    __syncthreads();
    uint32_t qf[4][4];
    {
        const int a_row = wid * 16 + (lane & 15);
        const int a_kof = (lane >> 4) * 8;
        #pragma unroll
        for (int t = 0; t < 4; t++)
            ldmx4(qf[t], sQ + (uint32_t)(a_row * FROWB + t * 16 + a_kof) * 2);
    }

    float O[8][4];
    #pragma unroll
    for (int j = 0; j < 8; j++)
        #pragma unroll
        for (int t = 0; t < 4; t++) O[j][t] = 0.f;
    float m_lo = -1e30f, m_hi = -1e30f, l_lo = 0.f, l_hi = 0.f;

    const int r_lo = q0 + wid * 16 + (lane >> 2);
    const int b_nrow = ((lane >> 4) << 3) + (lane & 7);
    const int b_kof  = ((lane >> 3) & 1) * 8;

    const int nt = 2 * qt + 2;
    for (int kt = 0; kt < nt; kt++) {
        const int buf = kt & 1;
        CP_WAIT0();
        __syncthreads();
        if (kt + 1 < nt) LOAD_KV(kt + 1, buf ^ 1);
        CP_COMMIT();

        const uint32_t kB  = sK  + (uint32_t)(buf * 64 * FROWB) * 2;
        const uint32_t vhB = sVh + (uint32_t)(buf * 64 * FROWB) * 2;
        const uint32_t vlB = sVl + (uint32_t)(buf * 64 * FROWB) * 2;

        float c[8][4];
        #pragma unroll
        for (int j = 0; j < 8; j++)
            #pragma unroll
            for (int t = 0; t < 4; t++) c[j][t] = 0.f;

        #pragma unroll
        for (int t = 0; t < 4; t++) {
            uint32_t kf[4][4];
            #pragma unroll
            for (int ng = 0; ng < 4; ng++)
                ldmx4(kf[ng], kB + (uint32_t)((ng * 16 + b_nrow) * FROWB + t * 16 + b_kof) * 2);
            #pragma unroll
            for (int nj = 0; nj < 8; nj++)
                mma16816(c[nj], qf[t], kf[nj >> 1][(nj & 1) * 2], kf[nj >> 1][(nj & 1) * 2 + 1]);
        }

        #pragma unroll
        for (int j = 0; j < 8; j++) {
            c[j][0] *= SCALE; c[j][1] *= SCALE; c[j][2] *= SCALE; c[j][3] *= SCALE;
        }

        if (kt >= 2 * qt) {
            const int col0 = kt * 64 + (lane & 3) * 2;
            #pragma unroll
            for (int j = 0; j < 8; j++) {
                const int cc = col0 + j * 8;
                if (cc     > r_lo)     c[j][0] = -1e30f;
                if (cc + 1 > r_lo)     c[j][1] = -1e30f;
                if (cc     > r_lo + 8) c[j][2] = -1e30f;
                if (cc + 1 > r_lo + 8) c[j][3] = -1e30f;
            }
        }

        float tmax_lo = c[0][0], tmax_hi = c[0][2];
        #pragma unroll
        for (int j = 0; j < 8; j++) {
            tmax_lo = fmaxf(tmax_lo, fmaxf(c[j][0], c[j][1]));
            tmax_hi = fmaxf(tmax_hi, fmaxf(c[j][2], c[j][3]));
        }
        tmax_lo = fmaxf(tmax_lo, __shfl_xor_sync(0xffffffffu, tmax_lo, 1));
        tmax_lo = fmaxf(tmax_lo, __shfl_xor_sync(0xffffffffu, tmax_lo, 2));
        tmax_hi = fmaxf(tmax_hi, __shfl_xor_sync(0xffffffffu, tmax_hi, 1));
        tmax_hi = fmaxf(tmax_hi, __shfl_xor_sync(0xffffffffu, tmax_hi, 2));

        const float mn_lo = fmaxf(m_lo, tmax_lo);
        const float mn_hi = fmaxf(m_hi, tmax_hi);
        const float sc_lo = __expf(m_lo - mn_lo);
        const float sc_hi = __expf(m_hi - mn_hi);
        m_lo = mn_lo; m_hi = mn_hi;

        float sum_lo = 0.f, sum_hi = 0.f;
        #pragma unroll
        for (int j = 0; j < 8; j++) {
            c[j][0] = __expf(c[j][0] - mn_lo);
            c[j][1] = __expf(c[j][1] - mn_lo);
            c[j][2] = __expf(c[j][2] - mn_hi);
            c[j][3] = __expf(c[j][3] - mn_hi);
            sum_lo += c[j][0] + c[j][1];
            sum_hi += c[j][2] + c[j][3];
        }
        sum_lo += __shfl_xor_sync(0xffffffffu, sum_lo, 1);
        sum_lo += __shfl_xor_sync(0xffffffffu, sum_lo, 2);
        sum_hi += __shfl_xor_sync(0xffffffffu, sum_hi, 1);
        sum_hi += __shfl_xor_sync(0xffffffffu, sum_hi, 2);
        l_lo = l_lo * sc_lo + sum_lo;
        l_hi = l_hi * sc_hi + sum_hi;

        #pragma unroll
        for (int j = 0; j < 8; j++) {
            O[j][0] *= sc_lo; O[j][1] *= sc_lo; O[j][2] *= sc_hi; O[j][3] *= sc_hi;
        }

        uint32_t ph[4][4], pl[4][4];
        #pragma unroll
        for (int t = 0; t < 4; t++) {
            const int j0 = 2 * t, j1 = 2 * t + 1;
            pack_split(c[j0][0], c[j0][1], ph[t][0], pl[t][0]);
            pack_split(c[j0][2], c[j0][3], ph[t][1], pl[t][1]);
            pack_split(c[j1][0], c[j1][1], ph[t][2], pl[t][2]);
            pack_split(c[j1][2], c[j1][3], ph[t][3], pl[t][3]);
        }

        #pragma unroll
        for (int t = 0; t < 4; t++) {
            uint32_t vbh[4][4], vbl[4][4];
            #pragma unroll
            for (int ng = 0; ng < 4; ng++) {
                ldmx4(vbh[ng], vhB + (uint32_t)((ng * 16 + b_nrow) * FROWB + t * 16 + b_kof) * 2);
                ldmx4(vbl[ng], vlB + (uint32_t)((ng * 16 + b_nrow) * FROWB + t * 16 + b_kof) * 2);
            }
            #pragma unroll
            for (int nj = 0; nj < 8; nj++) {
                const uint32_t bh0 = vbh[nj >> 1][(nj & 1) * 2], bh1 = vbh[nj >> 1][(nj & 1) * 2 + 1];
                const uint32_t bl0 = vbl[nj >> 1][(nj & 1) * 2], bl1 = vbl[nj >> 1][(nj & 1) * 2 + 1];
                mma16816(O[nj], ph[t], bh0, bh1);
                mma16816(O[nj], ph[t], bl0, bl1);
                mma16816(O[nj], pl[t], bh0, bh1);
            }
        }
    }

    const float inv_lo = 1.f / l_lo;
    const float inv_hi = 1.f / l_hi;
    #pragma unroll
    for (int j = 0; j < 8; j++) {
        const int col = h * HEAD + j * 8 + (lane & 3) * 2;
        *(float2*)&out[(size_t)(b * SEQ + r_lo) * H_DIM + col] =
            make_float2(O[j][0] * inv_lo, O[j][1] * inv_lo);
        *(float2*)&out[(size_t)(b * SEQ + r_lo + 8) * H_DIM + col] =
            make_float2(O[j][2] * inv_hi, O[j][3] * inv_hi);
    }
    #undef LOAD_KV
}

// ---------------------------------------------------------------------------
extern "C" void kernel_launch(void* const* d_in, const int* in_sizes, int n_in,
                              void* d_out, int out_size)
{
    const float* x  = (const float*)d_in[0];
    const float* Wq = (const float*)d_in[1];
    const float* bq = (const float*)d_in[2];
    const float* Wk = (const float*)d_in[3];
    const float* bk = (const float*)d_in[4];
    const float* Wv = (const float*)d_in[5];
    const float* bv = (const float*)d_in[6];
    float* out = (float*)d_out;

    cudaFuncSetAttribute(fattn_kernel,
                         cudaFuncAttributeMaxDynamicSharedMemorySize, ATTN_SMEM);

    convert_x_kernel<<<MROWS * H_DIM / 512, 256>>>(x);
    convert_w_kernel<<<NTOT * H_DIM / 512, 256>>>(Wq, Wk, Wv);

    dim3 ggrid(NTOT / 128, MROWS / 128);       // (24, 32)
    qkv_mma_kernel<<<ggrid, 256>>>(bq, bk, bv);

    dim3 vgrid(SEQ / 128, 32);                 // (16, 32)
    convert_v_kernel<<<vgrid, 256>>>();

    dim3 agrid(SEQ / 128, BATCH * NHEADS);     // (16, 32)
    fattn_kernel<<<agrid, 256, ATTN_SMEM>>>(out);
}

// round 7
// speedup vs baseline: 4.9103x; 1.0371x over previous
#include <cuda_runtime.h>
#include <cuda_bf16.h>
#include <cstdint>
#include <math.h>

#define H_DIM  1024
#define NHEADS 16
#define HEAD   64
#define BATCH  2
#define SEQ    2048
#define MROWS  (BATCH * SEQ)          // 4096
#define SC2    0.0450842410796f       // (1/32) * log2(e)
#define K2     2048                   // [hi | lo] expanded K
#define NTOT   3072                   // q|k|v output columns

// ---------------------------------------------------------------------------
// PTX helpers (arch-agnostic: mma.sync / ldmatrix / cp.async only)
// ---------------------------------------------------------------------------
__device__ __forceinline__ uint32_t smem_u32(const void* p) {
    uint32_t a;
    asm("{ .reg .u64 t; cvta.to.shared.u64 t, %1; cvt.u32.u64 %0, t; }" : "=r"(a) : "l"(p));
    return a;
}
__device__ __forceinline__ void cp_async16(uint32_t saddr, const void* gptr) {
    asm volatile("cp.async.cg.shared.global [%0], [%1], 16;" :: "r"(saddr), "l"(gptr) : "memory");
}
#define CP_COMMIT()  asm volatile("cp.async.commit_group;" ::: "memory")
#define CP_WAIT1()   asm volatile("cp.async.wait_group 1;" ::: "memory")
#define CP_WAIT0()   asm volatile("cp.async.wait_group 0;" ::: "memory")

__device__ __forceinline__ void ldmx4(uint32_t* r, uint32_t addr) {
    asm volatile("ldmatrix.sync.aligned.m8n8.x4.shared.b16 {%0,%1,%2,%3}, [%4];"
        : "=r"(r[0]), "=r"(r[1]), "=r"(r[2]), "=r"(r[3]) : "r"(addr));
}
__device__ __forceinline__ void mma16816(float* c, const uint32_t* a, uint32_t b0, uint32_t b1) {
    asm volatile("mma.sync.aligned.m16n8k16.row.col.f32.bf16.bf16.f32 "
        "{%0,%1,%2,%3}, {%4,%5,%6,%7}, {%8,%9}, {%0,%1,%2,%3};"
        : "+f"(c[0]), "+f"(c[1]), "+f"(c[2]), "+f"(c[3])
        : "r"(a[0]), "r"(a[1]), "r"(a[2]), "r"(a[3]), "r"(b0), "r"(b1));
}
__device__ __forceinline__ float ex2(float x) {
    float y;
    asm("ex2.approx.f32 %0, %1;" : "=f"(y) : "f"(x));
    return y;
}

__device__ __forceinline__ void pack_split(float a, float b, uint32_t& hi, uint32_t& lo) {
    __nv_bfloat16 ah = __float2bfloat16_rn(a), bh = __float2bfloat16_rn(b);
    __nv_bfloat162 h; h.x = ah; h.y = bh;
    hi = *(uint32_t*)&h;
    __nv_bfloat162 l;
    l.x = __float2bfloat16_rn(a - __bfloat162float(ah));
    l.y = __float2bfloat16_rn(b - __bfloat162float(bh));
    lo = *(uint32_t*)&l;
}

// ---------------------------------------------------------------------------
// Device scratch
// ---------------------------------------------------------------------------
__device__ float g_v[MROWS * H_DIM];                 // V projection fp32
__device__ __nv_bfloat16 g_qh[MROWS * H_DIM];        // Q bf16 [row, dim]
__device__ __nv_bfloat16 g_kh[MROWS * H_DIM];        // K bf16 [row, dim]
__device__ __nv_bfloat16 g_vth[32 * HEAD * SEQ];     // V^T hi  [bh][dim][key]
__device__ __nv_bfloat16 g_vtl[32 * HEAD * SEQ];     // V^T lo
__device__ __nv_bfloat16 g_Ax[MROWS * K2];           // [4096,2048] = [xh | xl]
__device__ __nv_bfloat16 g_Bx[NTOT * K2];            // rows n: [wh | wl]

// ---------------------------------------------------------------------------
// Conversion kernels (bf16 hi/lo split of x and W)
// ---------------------------------------------------------------------------
__device__ __forceinline__ void split2(float f, __nv_bfloat16& h, __nv_bfloat16& l) {
    h = __float2bfloat16_rn(f);
    l = __float2bfloat16_rn(f - __bfloat162float(h));
}

__global__ __launch_bounds__(256) void convert_x_kernel(const float* __restrict__ x)
{
    int i = blockIdx.x * 256 + threadIdx.x;
    int m = (2 * i) >> 10;
    int k = (2 * i) & 1023;
    float2 f = *(const float2*)&x[(size_t)2 * i];
    __nv_bfloat162 hh, ll;
    split2(f.x, hh.x, ll.x);
    split2(f.y, hh.y, ll.y);
    __nv_bfloat162* row = (__nv_bfloat162*)&g_Ax[(size_t)m * K2];
    row[(k) >> 1]        = hh;
    row[(k + 1024) >> 1] = ll;
}

__global__ __launch_bounds__(256) void convert_w_kernel(
    const float* __restrict__ Wq, const float* __restrict__ Wk, const float* __restrict__ Wv)
{
    int i = blockIdx.x * 256 + threadIdx.x;
    int n = (2 * i) >> 10;
    int k = (2 * i) & 1023;
    const float* W = (n < 1024) ? Wq : (n < 2048) ? Wk : Wv;
    float2 f = *(const float2*)&W[(size_t)(n & 1023) * 1024 + k];
    __nv_bfloat162 hh, ll;
    split2(f.x, hh.x, ll.x);
    split2(f.y, hh.y, ll.y);
    __nv_bfloat162* row = (__nv_bfloat162*)&g_Bx[(size_t)n * K2];
    row[(k) >> 1]        = hh;
    row[(k + 1024) >> 1] = ll;
}

// ---------------------------------------------------------------------------
// V transpose + hi/lo split:  g_v [b*2048+t][h*64+d] -> g_vth/l [bh][d][t]
// ---------------------------------------------------------------------------
__global__ __launch_bounds__(256) void convert_v_kernel()
{
    __shared__ float vt[128][65];
    const int kc = blockIdx.x;              // 128-key chunk, 0..15
    const int bh = blockIdx.y;              // 0..31
    const int b  = bh >> 4;
    const int h  = bh & 15;
    const int tid = threadIdx.x;

    #pragma unroll
    for (int i = 0; i < 32; i++) {
        int idx = tid + i * 256;            // 8192 = 128 keys x 64 dims
        int key = idx >> 6, d = idx & 63;
        vt[key][d] = g_v[(size_t)(b * SEQ + kc * 128 + key) * H_DIM + h * HEAD + d];
    }
    __syncthreads();
    #pragma unroll
    for (int i = 0; i < 32; i++) {
        int idx = tid + i * 256;
        int d = idx >> 7, key = idx & 127;
        float f = vt[key][d];
        __nv_bfloat16 hh = __float2bfloat16_rn(f);
        __nv_bfloat16 ll = __float2bfloat16_rn(f - __bfloat162float(hh));
        size_t o = ((size_t)bh * HEAD + d) * SEQ + kc * 128 + key;
        g_vth[o] = hh;
        g_vtl[o] = ll;
    }
}

// ---------------------------------------------------------------------------
// mma.sync GEMM:
//   Q/K tiles (n0 < 2048): single term  xh·wh^T            (32 K-chunks)
//   V tiles   (n0 >= 2048): xh·wh + xh·wl + xl·wh          (96 K-chunks)
// ---------------------------------------------------------------------------
#define BK        32
#define ROWB      40
#define BUF_ELE   (128 * ROWB)

__global__ __launch_bounds__(256) void qkv_mma_kernel(
    const float* __restrict__ bq, const float* __restrict__ bk, const float* __restrict__ bv)
{
    __shared__ __nv_bfloat16 Asm[2][BUF_ELE];
    __shared__ __nv_bfloat16 Bsm[2][BUF_ELE];

    const int tid  = threadIdx.x;
    const int wid  = tid >> 5;
    const int lane = tid & 31;
    const int wm   = wid & 3;
    const int wn   = wid >> 2;
    const int m0   = blockIdx.y * 128;
    const int n0   = blockIdx.x * 128;
    const int which = n0 >> 10;

    const uint32_t sA = smem_u32(Asm);
    const uint32_t sB = smem_u32(Bsm);

    const int row_s0 = tid >> 2,          seg_s0 = tid & 3;
    const int row_s1 = (tid + 256) >> 2,  seg_s1 = (tid + 256) & 3;

    #define LOAD_CHUNK(c, buf) do {                                             \
        const int t_   = (c) >> 5;                                              \
        const int kin_ = ((c) & 31) * BK;                                       \
        const int ao_  = (t_ == 2) ? 1024 : 0;                                  \
        const int bo_  = (t_ == 1) ? 1024 : 0;                                  \
        const __nv_bfloat16* ga0 = &g_Ax[(size_t)(m0 + row_s0) * K2 + ao_ + kin_ + seg_s0 * 8]; \
        const __nv_bfloat16* ga1 = &g_Ax[(size_t)(m0 + row_s1) * K2 + ao_ + kin_ + seg_s1 * 8]; \
        const __nv_bfloat16* gb0 = &g_Bx[(size_t)(n0 + row_s0) * K2 + bo_ + kin_ + seg_s0 * 8]; \
        const __nv_bfloat16* gb1 = &g_Bx[(size_t)(n0 + row_s1) * K2 + bo_ + kin_ + seg_s1 * 8]; \
        cp_async16(sA + (uint32_t)((buf) * BUF_ELE + row_s0 * ROWB + seg_s0 * 8) * 2, ga0);   \
        cp_async16(sA + (uint32_t)((buf) * BUF_ELE + row_s1 * ROWB + seg_s1 * 8) * 2, ga1);   \
        cp_async16(sB + (uint32_t)((buf) * BUF_ELE + row_s0 * ROWB + seg_s0 * 8) * 2, gb0);   \
        cp_async16(sB + (uint32_t)((buf) * BUF_ELE + row_s1 * ROWB + seg_s1 * 8) * 2, gb1);   \
    } while (0)

    float acc[2][8][4];
    #pragma unroll
    for (int mi = 0; mi < 2; mi++)
        #pragma unroll
        for (int nj = 0; nj < 8; nj++)
            #pragma unroll
            for (int t = 0; t < 4; t++) acc[mi][nj][t] = 0.f;

    const int a_row = wm * 32 + (lane & 15);
    const int a_kof = (lane >> 4) * 8;
    const int b_row_base = wn * 64 + ((lane >> 4) << 3) + (lane & 7);
    const int b_kof = ((lane >> 3) & 1) * 8;

    LOAD_CHUNK(0, 0); CP_COMMIT();
    LOAD_CHUNK(1, 1); CP_COMMIT();

    const int NCH = (which == 2) ? 96 : 32;
    for (int c = 0; c < NCH; c++) {
        const int buf = c & 1;
        CP_WAIT1();
        __syncthreads();

        const uint32_t aB = sA + (uint32_t)(buf * BUF_ELE) * 2;
        const uint32_t bB = sB + (uint32_t)(buf * BUF_ELE) * 2;

        #pragma unroll
        for (int ks = 0; ks < 2; ks++) {
            const int k0 = ks * 16;
            uint32_t afr[2][4];
            #pragma unroll
            for (int mi = 0; mi < 2; mi++)
                ldmx4(afr[mi], aB + (uint32_t)((a_row + mi * 16) * ROWB + k0 + a_kof) * 2);
            uint32_t bfr[4][4];
            #pragma unroll
            for (int ni = 0; ni < 4; ni++)
                ldmx4(bfr[ni], bB + (uint32_t)((b_row_base + ni * 16) * ROWB + k0 + b_kof) * 2);
            #pragma unroll
            for (int mi = 0; mi < 2; mi++)
                #pragma unroll
                for (int nj = 0; nj < 8; nj++)
                    mma16816(acc[mi][nj], afr[mi],
                             bfr[nj >> 1][(nj & 1) * 2], bfr[nj >> 1][(nj & 1) * 2 + 1]);
        }

        __syncthreads();
        if (c + 2 < NCH) LOAD_CHUNK(c + 2, buf);
        CP_COMMIT();
    }

    // ---- epilogue ----
    const float* bias = (which == 0) ? bq : (which == 1) ? bk : bv;
    const int nn0 = n0 & 1023;

    #pragma unroll
    for (int mi = 0; mi < 2; mi++) {
        const int r0 = m0 + wm * 32 + mi * 16 + (lane >> 2);
        #pragma unroll
        for (int nj = 0; nj < 8; nj++) {
            const int col = nn0 + wn * 64 + nj * 8 + (lane & 3) * 2;
            const float2 bb = *(const float2*)&bias[col];
            float lox = acc[mi][nj][0] + bb.x, loy = acc[mi][nj][1] + bb.y;
            float hix = acc[mi][nj][2] + bb.x, hiy = acc[mi][nj][3] + bb.y;
            if (which == 2) {
                *(float2*)&g_v[(size_t)r0 * H_DIM + col]       = make_float2(lox, loy);
                *(float2*)&g_v[(size_t)(r0 + 8) * H_DIM + col] = make_float2(hix, hiy);
            } else {
                __nv_bfloat16* ob = (which == 0) ? g_qh : g_kh;
                __nv_bfloat162 plo; plo.x = __float2bfloat16_rn(lox); plo.y = __float2bfloat16_rn(loy);
                __nv_bfloat162 phi; phi.x = __float2bfloat16_rn(hix); phi.y = __float2bfloat16_rn(hiy);
                *(__nv_bfloat162*)&ob[(size_t)r0 * H_DIM + col]       = plo;
                *(__nv_bfloat162*)&ob[(size_t)(r0 + 8) * H_DIM + col] = phi;
            }
        }
    }
    #undef LOAD_CHUNK
}

// ---------------------------------------------------------------------------
// FlashAttention-2 causal attention, mma.sync.
// CTA: 64 q-rows x one (b,h), 4 warps (16-row stripe each), 64-key tiles.
// 1024 CTAs, ~2 resident/SM → latency hiding; only diagonal tile masked.
// ---------------------------------------------------------------------------
#define FROWB    72
#define QS_BYTES (64 * FROWB * 2)                  // 9216
#define KV_BUF   (64 * FROWB * 2)                  // 9216
#define KS_OFF   QS_BYTES
#define VH_OFF   (KS_OFF + 2 * KV_BUF)
#define VL_OFF   (VH_OFF + 2 * KV_BUF)
#define ATTN_SMEM (VL_OFF + 2 * KV_BUF)            // 64512

__global__ __launch_bounds__(128) void fattn_kernel(float* __restrict__ out)
{
    extern __shared__ char sm[];
    const uint32_t sQ  = smem_u32(sm);
    const uint32_t sK  = sQ + KS_OFF;
    const uint32_t sVh = sQ + VH_OFF;
    const uint32_t sVl = sQ + VL_OFF;

    const int qt  = (gridDim.x - 1) - blockIdx.x;   // heavy tiles first
    const int bh  = blockIdx.y;
    const int b   = bh >> 4;
    const int h   = bh & 15;
    const int q0  = qt * 64;
    const int tid = threadIdx.x;
    const int wid = tid >> 5;
    const int lane = tid & 31;

    // ---- Q tile (64 rows x 64 dims) ----
    #pragma unroll
    for (int i = 0; i < 4; i++) {
        int id = tid + i * 128; int row = id >> 3; int seg = id & 7;
        cp_async16(sQ + (uint32_t)(row * FROWB + seg * 8) * 2,
                   &g_qh[(size_t)(b * SEQ + q0 + row) * H_DIM + h * HEAD + seg * 8]);
    }
    CP_COMMIT();

    #define LOAD_KV(kt_, buf_) do {                                            \
        const int k0_ = (kt_) * 64;                                            \
        _Pragma("unroll")                                                      \
        for (int i = 0; i < 4; i++) {                                          \
            int id = tid + i * 128; int row = id >> 3; int seg = id & 7;       \
            cp_async16(sK + (uint32_t)((buf_) * (64 * FROWB) + row * FROWB + seg * 8) * 2, \
                &g_kh[(size_t)(b * SEQ + k0_ + row) * H_DIM + h * HEAD + seg * 8]); \
            cp_async16(sVh + (uint32_t)((buf_) * (64 * FROWB) + row * FROWB + seg * 8) * 2, \
                &g_vth[((size_t)bh * HEAD + row) * SEQ + k0_ + seg * 8]);      \
            cp_async16(sVl + (uint32_t)((buf_) * (64 * FROWB) + row * FROWB + seg * 8) * 2, \
                &g_vtl[((size_t)bh * HEAD + row) * SEQ + k0_ + seg * 8]);      \
        }                                                                      \
    } while (0)

    LOAD_KV(0, 0);
    CP_COMMIT();

    // ---- wait Q, build Q A-frags ----
    CP_WAIT1();
    __syncthreads();
    uint32_t qf[4][4];
    {
        const int a_row = wid * 16 + (lane & 15);
        const int a_kof = (lane >> 4) * 8;
        #pragma unroll
        for (int t = 0; t < 4; t++)
            ldmx4(qf[t], sQ + (uint32_t)(a_row * FROWB + t * 16 + a_kof) * 2);
    }

    float O[8][4];
    #pragma unroll
    for (int j = 0; j < 8; j++)
        #pragma unroll
        for (int t = 0; t < 4; t++) O[j][t] = 0.f;
    float m_lo = -1e30f, m_hi = -1e30f, l_lo = 0.f, l_hi = 0.f;

    const int r_lo = q0 + wid * 16 + (lane >> 2);
    const int b_nrow = ((lane >> 4) << 3) + (lane & 7);
    const int b_kof  = ((lane >> 3) & 1) * 8;

    const int nt = qt + 1;
    for (int kt = 0; kt < nt; kt++) {
        const int buf = kt & 1;
        CP_WAIT0();
        __syncthreads();
        if (kt + 1 < nt) LOAD_KV(kt + 1, buf ^ 1);
        CP_COMMIT();

        const uint32_t kB  = sK  + (uint32_t)(buf * 64 * FROWB) * 2;
        const uint32_t vhB = sVh + (uint32_t)(buf * 64 * FROWB) * 2;
        const uint32_t vlB = sVl + (uint32_t)(buf * 64 * FROWB) * 2;

        // ---- S = Q K^T (log2-domain scaling) ----
        float c[8][4];
        #pragma unroll
        for (int j = 0; j < 8; j++)
            #pragma unroll
            for (int t = 0; t < 4; t++) c[j][t] = 0.f;

        #pragma unroll
        for (int t = 0; t < 4; t++) {
            uint32_t kf[4][4];
            #pragma unroll
            for (int ng = 0; ng < 4; ng++)
                ldmx4(kf[ng], kB + (uint32_t)((ng * 16 + b_nrow) * FROWB + t * 16 + b_kof) * 2);
            #pragma unroll
            for (int nj = 0; nj < 8; nj++)
                mma16816(c[nj], qf[t], kf[nj >> 1][(nj & 1) * 2], kf[nj >> 1][(nj & 1) * 2 + 1]);
        }

        #pragma unroll
        for (int j = 0; j < 8; j++) {
            c[j][0] *= SC2; c[j][1] *= SC2; c[j][2] *= SC2; c[j][3] *= SC2;
        }

        // ---- causal mask (diagonal tile only) ----
        if (kt == qt) {
            const int col0 = kt * 64 + (lane & 3) * 2;
            #pragma unroll
            for (int j = 0; j < 8; j++) {
                const int cc = col0 + j * 8;
                if (cc     > r_lo)     c[j][0] = -1e30f;
                if (cc + 1 > r_lo)     c[j][1] = -1e30f;
                if (cc     > r_lo + 8) c[j][2] = -1e30f;
                if (cc + 1 > r_lo + 8) c[j][3] = -1e30f;
            }
        }

        // ---- online softmax (base-2) ----
        float tmax_lo = c[0][0], tmax_hi = c[0][2];
        #pragma unroll
        for (int j = 0; j < 8; j++) {
            tmax_lo = fmaxf(tmax_lo, fmaxf(c[j][0], c[j][1]));
            tmax_hi = fmaxf(tmax_hi, fmaxf(c[j][2], c[j][3]));
        }
        tmax_lo = fmaxf(tmax_lo, __shfl_xor_sync(0xffffffffu, tmax_lo, 1));
        tmax_lo = fmaxf(tmax_lo, __shfl_xor_sync(0xffffffffu, tmax_lo, 2));
        tmax_hi = fmaxf(tmax_hi, __shfl_xor_sync(0xffffffffu, tmax_hi, 1));
        tmax_hi = fmaxf(tmax_hi, __shfl_xor_sync(0xffffffffu, tmax_hi, 2));

        const float mn_lo = fmaxf(m_lo, tmax_lo);
        const float mn_hi = fmaxf(m_hi, tmax_hi);
        const float sc_lo = ex2(m_lo - mn_lo);
        const float sc_hi = ex2(m_hi - mn_hi);
        m_lo = mn_lo; m_hi = mn_hi;

        float sum_lo = 0.f, sum_hi = 0.f;
        #pragma unroll
        for (int j = 0; j < 8; j++) {
            c[j][0] = ex2(c[j][0] - mn_lo);
            c[j][1] = ex2(c[j][1] - mn_lo);
            c[j][2] = ex2(c[j][2] - mn_hi);
            c[j][3] = ex2(c[j][3] - mn_hi);
            sum_lo += c[j][0] + c[j][1];
            sum_hi += c[j][2] + c[j][3];
        }
        sum_lo += __shfl_xor_sync(0xffffffffu, sum_lo, 1);
        sum_lo += __shfl_xor_sync(0xffffffffu, sum_lo, 2);
        sum_hi += __shfl_xor_sync(0xffffffffu, sum_hi, 1);
        sum_hi += __shfl_xor_sync(0xffffffffu, sum_hi, 2);
        l_lo = l_lo * sc_lo + sum_lo;
        l_hi = l_hi * sc_hi + sum_hi;

        #pragma unroll
        for (int j = 0; j < 8; j++) {
            O[j][0] *= sc_lo; O[j][1] *= sc_lo; O[j][2] *= sc_hi; O[j][3] *= sc_hi;
        }

        // ---- pack P hi/lo A-frags ----
        uint32_t ph[4][4], pl[4][4];
        #pragma unroll
        for (int t = 0; t < 4; t++) {
            const int j0 = 2 * t, j1 = 2 * t + 1;
            pack_split(c[j0][0], c[j0][1], ph[t][0], pl[t][0]);
            pack_split(c[j0][2], c[j0][3], ph[t][1], pl[t][1]);
            pack_split(c[j1][0], c[j1][1], ph[t][2], pl[t][2]);
            pack_split(c[j1][2], c[j1][3], ph[t][3], pl[t][3]);
        }

        // ---- O += ph*Vh + ph*Vl + pl*Vh ----
        #pragma unroll
        for (int t = 0; t < 4; t++) {
            uint32_t vbh[4][4], vbl[4][4];
            #pragma unroll
            for (int ng = 0; ng < 4; ng++) {
                ldmx4(vbh[ng], vhB + (uint32_t)((ng * 16 + b_nrow) * FROWB + t * 16 + b_kof) * 2);
                ldmx4(vbl[ng], vlB + (uint32_t)((ng * 16 + b_nrow) * FROWB + t * 16 + b_kof) * 2);
            }
            #pragma unroll
            for (int nj = 0; nj < 8; nj++) {
                const uint32_t bh0 = vbh[nj >> 1][(nj & 1) * 2], bh1 = vbh[nj >> 1][(nj & 1) * 2 + 1];
                const uint32_t bl0 = vbl[nj >> 1][(nj & 1) * 2], bl1 = vbl[nj >> 1][(nj & 1) * 2 + 1];
                mma16816(O[nj], ph[t], bh0, bh1);
                mma16816(O[nj], ph[t], bl0, bl1);
                mma16816(O[nj], pl[t], bh0, bh1);
            }
        }
    }

    // ---- epilogue ----
    const float inv_lo = 1.f / l_lo;
    const float inv_hi = 1.f / l_hi;
    #pragma unroll
    for (int j = 0; j < 8; j++) {
        const int col = h * HEAD + j * 8 + (lane & 3) * 2;
        *(float2*)&out[(size_t)(b * SEQ + r_lo) * H_DIM + col] =
            make_float2(O[j][0] * inv_lo, O[j][1] * inv_lo);
        *(float2*)&out[(size_t)(b * SEQ + r_lo + 8) * H_DIM + col] =
            make_float2(O[j][2] * inv_hi, O[j][3] * inv_hi);
    }
    #undef LOAD_KV
}

// ---------------------------------------------------------------------------
extern "C" void kernel_launch(void* const* d_in, const int* in_sizes, int n_in,
                              void* d_out, int out_size)
{
    const float* x  = (const float*)d_in[0];
    const float* Wq = (const float*)d_in[1];
    const float* bq = (const float*)d_in[2];
    const float* Wk = (const float*)d_in[3];
    const float* bk = (const float*)d_in[4];
    const float* Wv = (const float*)d_in[5];
    const float* bv = (const float*)d_in[6];
    float* out = (float*)d_out;

    cudaFuncSetAttribute(fattn_kernel,
                         cudaFuncAttributeMaxDynamicSharedMemorySize, ATTN_SMEM);

    convert_x_kernel<<<MROWS * H_DIM / 512, 256>>>(x);
    convert_w_kernel<<<NTOT * H_DIM / 512, 256>>>(Wq, Wk, Wv);

    dim3 ggrid(NTOT / 128, MROWS / 128);       // (24, 32)
    qkv_mma_kernel<<<ggrid, 256>>>(bq, bk, bv);

    dim3 vgrid(SEQ / 128, 32);                 // (16, 32)
    convert_v_kernel<<<vgrid, 256>>>();

    dim3 agrid(SEQ / 64, BATCH * NHEADS);      // (32, 32)
    fattn_kernel<<<agrid, 128, ATTN_SMEM>>>(out);
}

// round 8
// speedup vs baseline: 5.9286x; 1.2074x over previous
#include <cuda_runtime.h>
#include <cuda_bf16.h>
#include <cuda_fp16.h>
#include <cstdint>
#include <math.h>

#define H_DIM  1024
#define NHEADS 16
#define HEAD   64
#define BATCH  2
#define SEQ    2048
#define MROWS  (BATCH * SEQ)          // 4096
#define SC2    0.0450842410796f       // (1/32) * log2(e)
#define K2     2048                   // [hi | lo] expanded K
#define NTOT   3072                   // q|k|v output columns

// ---------------------------------------------------------------------------
// PTX helpers
// ---------------------------------------------------------------------------
__device__ __forceinline__ uint32_t smem_u32(const void* p) {
    uint32_t a;
    asm("{ .reg .u64 t; cvta.to.shared.u64 t, %1; cvt.u32.u64 %0, t; }" : "=r"(a) : "l"(p));
    return a;
}
__device__ __forceinline__ void cp_async16(uint32_t saddr, const void* gptr) {
    asm volatile("cp.async.cg.shared.global [%0], [%1], 16;" :: "r"(saddr), "l"(gptr) : "memory");
}
#define CP_COMMIT()  asm volatile("cp.async.commit_group;" ::: "memory")
#define CP_WAIT1()   asm volatile("cp.async.wait_group 1;" ::: "memory")
#define CP_WAIT0()   asm volatile("cp.async.wait_group 0;" ::: "memory")

__device__ __forceinline__ void ldmx4(uint32_t* r, uint32_t addr) {
    asm volatile("ldmatrix.sync.aligned.m8n8.x4.shared.b16 {%0,%1,%2,%3}, [%4];"
        : "=r"(r[0]), "=r"(r[1]), "=r"(r[2]), "=r"(r[3]) : "r"(addr));
}
// bf16 variant (QKV projection GEMM)
__device__ __forceinline__ void mma16816(float* c, const uint32_t* a, uint32_t b0, uint32_t b1) {
    asm volatile("mma.sync.aligned.m16n8k16.row.col.f32.bf16.bf16.f32 "
        "{%0,%1,%2,%3}, {%4,%5,%6,%7}, {%8,%9}, {%0,%1,%2,%3};"
        : "+f"(c[0]), "+f"(c[1]), "+f"(c[2]), "+f"(c[3])
        : "r"(a[0]), "r"(a[1]), "r"(a[2]), "r"(a[3]), "r"(b0), "r"(b1));
}
// fp16 variant (attention)
__device__ __forceinline__ void mma16816h(float* c, const uint32_t* a, uint32_t b0, uint32_t b1) {
    asm volatile("mma.sync.aligned.m16n8k16.row.col.f32.f16.f16.f32 "
        "{%0,%1,%2,%3}, {%4,%5,%6,%7}, {%8,%9}, {%0,%1,%2,%3};"
        : "+f"(c[0]), "+f"(c[1]), "+f"(c[2]), "+f"(c[3])
        : "r"(a[0]), "r"(a[1]), "r"(a[2]), "r"(a[3]), "r"(b0), "r"(b1));
}
__device__ __forceinline__ float ex2(float x) {
    float y;
    asm("ex2.approx.f32 %0, %1;" : "=f"(y) : "f"(x));
    return y;
}
__device__ __forceinline__ uint32_t pack_h2(float a, float b) {
    __half2 h = __floats2half2_rn(a, b);
    return *(uint32_t*)&h;
}

// ---------------------------------------------------------------------------
// Device scratch
// ---------------------------------------------------------------------------
__device__ float g_v[MROWS * H_DIM];                 // V projection fp32
__device__ __half g_qh[MROWS * H_DIM];               // Q fp16 [row, dim]
__device__ __half g_kh[MROWS * H_DIM];               // K fp16 [row, dim]
__device__ __half g_vth[32 * HEAD * SEQ];            // V^T fp16 [bh][dim][key]
__device__ __nv_bfloat16 g_Ax[MROWS * K2];           // [4096,2048] = [xh | xl]
__device__ __nv_bfloat16 g_Bx[NTOT * K2];            // rows n: [wh | wl]

// ---------------------------------------------------------------------------
// Conversion kernels (bf16 hi/lo split of x and W)
// ---------------------------------------------------------------------------
__device__ __forceinline__ void split2(float f, __nv_bfloat16& h, __nv_bfloat16& l) {
    h = __float2bfloat16_rn(f);
    l = __float2bfloat16_rn(f - __bfloat162float(h));
}

__global__ __launch_bounds__(256) void convert_x_kernel(const float* __restrict__ x)
{
    int i = blockIdx.x * 256 + threadIdx.x;
    int m = (2 * i) >> 10;
    int k = (2 * i) & 1023;
    float2 f = *(const float2*)&x[(size_t)2 * i];
    __nv_bfloat162 hh, ll;
    split2(f.x, hh.x, ll.x);
    split2(f.y, hh.y, ll.y);
    __nv_bfloat162* row = (__nv_bfloat162*)&g_Ax[(size_t)m * K2];
    row[(k) >> 1]        = hh;
    row[(k + 1024) >> 1] = ll;
}

__global__ __launch_bounds__(256) void convert_w_kernel(
    const float* __restrict__ Wq, const float* __restrict__ Wk, const float* __restrict__ Wv)
{
    int i = blockIdx.x * 256 + threadIdx.x;
    int n = (2 * i) >> 10;
    int k = (2 * i) & 1023;
    const float* W = (n < 1024) ? Wq : (n < 2048) ? Wk : Wv;
    float2 f = *(const float2*)&W[(size_t)(n & 1023) * 1024 + k];
    __nv_bfloat162 hh, ll;
    split2(f.x, hh.x, ll.x);
    split2(f.y, hh.y, ll.y);
    __nv_bfloat162* row = (__nv_bfloat162*)&g_Bx[(size_t)n * K2];
    row[(k) >> 1]        = hh;
    row[(k + 1024) >> 1] = ll;
}

// ---------------------------------------------------------------------------
// V transpose:  g_v [b*2048+t][h*64+d] (fp32) -> g_vth [bh][d][t] (fp16)
// ---------------------------------------------------------------------------
__global__ __launch_bounds__(256) void convert_v_kernel()
{
    __shared__ float vt[128][65];
    const int kc = blockIdx.x;              // 128-key chunk, 0..15
    const int bh = blockIdx.y;              // 0..31
    const int b  = bh >> 4;
    const int h  = bh & 15;
    const int tid = threadIdx.x;

    #pragma unroll
    for (int i = 0; i < 32; i++) {
        int idx = tid + i * 256;            // 8192 = 128 keys x 64 dims
        int key = idx >> 6, d = idx & 63;
        vt[key][d] = g_v[(size_t)(b * SEQ + kc * 128 + key) * H_DIM + h * HEAD + d];
    }
    __syncthreads();
    #pragma unroll
    for (int i = 0; i < 32; i++) {
        int idx = tid + i * 256;
        int d = idx >> 7, key = idx & 127;
        g_vth[((size_t)bh * HEAD + d) * SEQ + kc * 128 + key] = __float2half_rn(vt[key][d]);
    }
}

// ---------------------------------------------------------------------------
// mma.sync GEMM:
//   Q/K tiles (n0 < 2048): single term  xh·wh^T            (32 K-chunks)
//   V tiles   (n0 >= 2048): xh·wh + xh·wl + xl·wh          (96 K-chunks)
// ---------------------------------------------------------------------------
#define BK        32
#define ROWB      40
#define BUF_ELE   (128 * ROWB)

__global__ __launch_bounds__(256) void qkv_mma_kernel(
    const float* __restrict__ bq, const float* __restrict__ bk, const float* __restrict__ bv)
{
    __shared__ __nv_bfloat16 Asm[2][BUF_ELE];
    __shared__ __nv_bfloat16 Bsm[2][BUF_ELE];

    const int tid  = threadIdx.x;
    const int wid  = tid >> 5;
    const int lane = tid & 31;
    const int wm   = wid & 3;
    const int wn   = wid >> 2;
    const int m0   = blockIdx.y * 128;
    const int n0   = blockIdx.x * 128;
    const int which = n0 >> 10;

    const uint32_t sA = smem_u32(Asm);
    const uint32_t sB = smem_u32(Bsm);

    const int row_s0 = tid >> 2,          seg_s0 = tid & 3;
    const int row_s1 = (tid + 256) >> 2,  seg_s1 = (tid + 256) & 3;

    #define LOAD_CHUNK(c, buf) do {                                             \
        const int t_   = (c) >> 5;                                              \
        const int kin_ = ((c) & 31) * BK;                                       \
        const int ao_  = (t_ == 2) ? 1024 : 0;                                  \
        const int bo_  = (t_ == 1) ? 1024 : 0;                                  \
        const __nv_bfloat16* ga0 = &g_Ax[(size_t)(m0 + row_s0) * K2 + ao_ + kin_ + seg_s0 * 8]; \
        const __nv_bfloat16* ga1 = &g_Ax[(size_t)(m0 + row_s1) * K2 + ao_ + kin_ + seg_s1 * 8]; \
        const __nv_bfloat16* gb0 = &g_Bx[(size_t)(n0 + row_s0) * K2 + bo_ + kin_ + seg_s0 * 8]; \
        const __nv_bfloat16* gb1 = &g_Bx[(size_t)(n0 + row_s1) * K2 + bo_ + kin_ + seg_s1 * 8]; \
        cp_async16(sA + (uint32_t)((buf) * BUF_ELE + row_s0 * ROWB + seg_s0 * 8) * 2, ga0);   \
        cp_async16(sA + (uint32_t)((buf) * BUF_ELE + row_s1 * ROWB + seg_s1 * 8) * 2, ga1);   \
        cp_async16(sB + (uint32_t)((buf) * BUF_ELE + row_s0 * ROWB + seg_s0 * 8) * 2, gb0);   \
        cp_async16(sB + (uint32_t)((buf) * BUF_ELE + row_s1 * ROWB + seg_s1 * 8) * 2, gb1);   \
    } while (0)

    float acc[2][8][4];
    #pragma unroll
    for (int mi = 0; mi < 2; mi++)
        #pragma unroll
        for (int nj = 0; nj < 8; nj++)
            #pragma unroll
            for (int t = 0; t < 4; t++) acc[mi][nj][t] = 0.f;

    const int a_row = wm * 32 + (lane & 15);
    const int a_kof = (lane >> 4) * 8;
    const int b_row_base = wn * 64 + ((lane >> 4) << 3) + (lane & 7);
    const int b_kof = ((lane >> 3) & 1) * 8;

    LOAD_CHUNK(0, 0); CP_COMMIT();
    LOAD_CHUNK(1, 1); CP_COMMIT();

    const int NCH = (which == 2) ? 96 : 32;
    for (int c = 0; c < NCH; c++) {
        const int buf = c & 1;
        CP_WAIT1();
        __syncthreads();

        const uint32_t aB = sA + (uint32_t)(buf * BUF_ELE) * 2;
        const uint32_t bB = sB + (uint32_t)(buf * BUF_ELE) * 2;

        #pragma unroll
        for (int ks = 0; ks < 2; ks++) {
            const int k0 = ks * 16;
            uint32_t afr[2][4];
            #pragma unroll
            for (int mi = 0; mi < 2; mi++)
                ldmx4(afr[mi], aB + (uint32_t)((a_row + mi * 16) * ROWB + k0 + a_kof) * 2);
            uint32_t bfr[4][4];
            #pragma unroll
            for (int ni = 0; ni < 4; ni++)
                ldmx4(bfr[ni], bB + (uint32_t)((b_row_base + ni * 16) * ROWB + k0 + b_kof) * 2);
            #pragma unroll
            for (int mi = 0; mi < 2; mi++)
                #pragma unroll
                for (int nj = 0; nj < 8; nj++)
                    mma16816(acc[mi][nj], afr[mi],
                             bfr[nj >> 1][(nj & 1) * 2], bfr[nj >> 1][(nj & 1) * 2 + 1]);
        }

        __syncthreads();
        if (c + 2 < NCH) LOAD_CHUNK(c + 2, buf);
        CP_COMMIT();
    }

    // ---- epilogue ----
    const float* bias = (which == 0) ? bq : (which == 1) ? bk : bv;
    const int nn0 = n0 & 1023;

    #pragma unroll
    for (int mi = 0; mi < 2; mi++) {
        const int r0 = m0 + wm * 32 + mi * 16 + (lane >> 2);
        #pragma unroll
        for (int nj = 0; nj < 8; nj++) {
            const int col = nn0 + wn * 64 + nj * 8 + (lane & 3) * 2;
            const float2 bb = *(const float2*)&bias[col];
            float lox = acc[mi][nj][0] + bb.x, loy = acc[mi][nj][1] + bb.y;
            float hix = acc[mi][nj][2] + bb.x, hiy = acc[mi][nj][3] + bb.y;
            if (which == 2) {
                *(float2*)&g_v[(size_t)r0 * H_DIM + col]       = make_float2(lox, loy);
                *(float2*)&g_v[(size_t)(r0 + 8) * H_DIM + col] = make_float2(hix, hiy);
            } else {
                __half* ob = (which == 0) ? g_qh : g_kh;
                *(__half2*)&ob[(size_t)r0 * H_DIM + col]       = __floats2half2_rn(lox, loy);
                *(__half2*)&ob[(size_t)(r0 + 8) * H_DIM + col] = __floats2half2_rn(hix, hiy);
            }
        }
    }
    #undef LOAD_CHUNK
}

// ---------------------------------------------------------------------------
// FlashAttention-2 causal attention, fp16 mma.sync.
// CTA: 64 q-rows x one (b,h), 4 warps (16-row stripe each), 64-key tiles.
// ---------------------------------------------------------------------------
#define FROWB    72
#define QS_BYTES (64 * FROWB * 2)                  // 9216
#define KV_BUF   (64 * FROWB * 2)                  // 9216
#define KS_OFF   QS_BYTES
#define VH_OFF   (KS_OFF + 2 * KV_BUF)
#define ATTN_SMEM (VH_OFF + 2 * KV_BUF)            // 46080

__global__ __launch_bounds__(128) void fattn_kernel(float* __restrict__ out)
{
    extern __shared__ char sm[];
    const uint32_t sQ  = smem_u32(sm);
    const uint32_t sK  = sQ + KS_OFF;
    const uint32_t sVt = sQ + VH_OFF;

    const int qt  = (gridDim.x - 1) - blockIdx.x;   // heavy tiles first
    const int bh  = blockIdx.y;
    const int b   = bh >> 4;
    const int h   = bh & 15;
    const int q0  = qt * 64;
    const int tid = threadIdx.x;
    const int wid = tid >> 5;
    const int lane = tid & 31;

    // ---- Q tile (64 rows x 64 dims) ----
    #pragma unroll
    for (int i = 0; i < 4; i++) {
        int id = tid + i * 128; int row = id >> 3; int seg = id & 7;
        cp_async16(sQ + (uint32_t)(row * FROWB + seg * 8) * 2,
                   &g_qh[(size_t)(b * SEQ + q0 + row) * H_DIM + h * HEAD + seg * 8]);
    }
    CP_COMMIT();

    #define LOAD_KV(kt_, buf_) do {                                            \
        const int k0_ = (kt_) * 64;                                            \
        _Pragma("unroll")                                                      \
        for (int i = 0; i < 4; i++) {                                          \
            int id = tid + i * 128; int row = id >> 3; int seg = id & 7;       \
            cp_async16(sK + (uint32_t)((buf_) * (64 * FROWB) + row * FROWB + seg * 8) * 2, \
                &g_kh[(size_t)(b * SEQ + k0_ + row) * H_DIM + h * HEAD + seg * 8]); \
            cp_async16(sVt + (uint32_t)((buf_) * (64 * FROWB) + row * FROWB + seg * 8) * 2, \
                &g_vth[((size_t)bh * HEAD + row) * SEQ + k0_ + seg * 8]);      \
        }                                                                      \
    } while (0)

    LOAD_KV(0, 0);
    CP_COMMIT();

    // ---- wait Q, build Q A-frags ----
    CP_WAIT1();
    __syncthreads();
    uint32_t qf[4][4];
    {
        const int a_row = wid * 16 + (lane & 15);
        const int a_kof = (lane >> 4) * 8;
        #pragma unroll
        for (int t = 0; t < 4; t++)
            ldmx4(qf[t], sQ + (uint32_t)(a_row * FROWB + t * 16 + a_kof) * 2);
    }

    float O[8][4];
    #pragma unroll
    for (int j = 0; j < 8; j++)
        #pragma unroll
        for (int t = 0; t < 4; t++) O[j][t] = 0.f;
    float m_lo = -1e30f, m_hi = -1e30f, l_lo = 0.f, l_hi = 0.f;

    const int r_lo = q0 + wid * 16 + (lane >> 2);
    const int b_nrow = ((lane >> 4) << 3) + (lane & 7);
    const int b_kof  = ((lane >> 3) & 1) * 8;

    const int nt = qt + 1;
    for (int kt = 0; kt < nt; kt++) {
        const int buf = kt & 1;
        CP_WAIT0();
        __syncthreads();
        if (kt + 1 < nt) LOAD_KV(kt + 1, buf ^ 1);
        CP_COMMIT();

        const uint32_t kB  = sK  + (uint32_t)(buf * 64 * FROWB) * 2;
        const uint32_t vtB = sVt + (uint32_t)(buf * 64 * FROWB) * 2;

        // ---- S = Q K^T ----
        float c[8][4];
        #pragma unroll
        for (int j = 0; j < 8; j++)
            #pragma unroll
            for (int t = 0; t < 4; t++) c[j][t] = 0.f;

        #pragma unroll
        for (int t = 0; t < 4; t++) {
            uint32_t kf[4][4];
            #pragma unroll
            for (int ng = 0; ng < 4; ng++)
                ldmx4(kf[ng], kB + (uint32_t)((ng * 16 + b_nrow) * FROWB + t * 16 + b_kof) * 2);
            #pragma unroll
            for (int nj = 0; nj < 8; nj++)
                mma16816h(c[nj], qf[t], kf[nj >> 1][(nj & 1) * 2], kf[nj >> 1][(nj & 1) * 2 + 1]);
        }

        #pragma unroll
        for (int j = 0; j < 8; j++) {
            c[j][0] *= SC2; c[j][1] *= SC2; c[j][2] *= SC2; c[j][3] *= SC2;
        }

        // ---- causal mask (diagonal tile only) ----
        if (kt == qt) {
            const int col0 = kt * 64 + (lane & 3) * 2;
            #pragma unroll
            for (int j = 0; j < 8; j++) {
                const int cc = col0 + j * 8;
                if (cc     > r_lo)     c[j][0] = -1e30f;
                if (cc + 1 > r_lo)     c[j][1] = -1e30f;
                if (cc     > r_lo + 8) c[j][2] = -1e30f;
                if (cc + 1 > r_lo + 8) c[j][3] = -1e30f;
            }
        }

        // ---- online softmax (base-2) ----
        float tmax_lo = c[0][0], tmax_hi = c[0][2];
        #pragma unroll
        for (int j = 0; j < 8; j++) {
            tmax_lo = fmaxf(tmax_lo, fmaxf(c[j][0], c[j][1]));
            tmax_hi = fmaxf(tmax_hi, fmaxf(c[j][2], c[j][3]));
        }
        tmax_lo = fmaxf(tmax_lo, __shfl_xor_sync(0xffffffffu, tmax_lo, 1));
        tmax_lo = fmaxf(tmax_lo, __shfl_xor_sync(0xffffffffu, tmax_lo, 2));
        tmax_hi = fmaxf(tmax_hi, __shfl_xor_sync(0xffffffffu, tmax_hi, 1));
        tmax_hi = fmaxf(tmax_hi, __shfl_xor_sync(0xffffffffu, tmax_hi, 2));

        const float mn_lo = fmaxf(m_lo, tmax_lo);
        const float mn_hi = fmaxf(m_hi, tmax_hi);
        const float sc_lo = ex2(m_lo - mn_lo);
        const float sc_hi = ex2(m_hi - mn_hi);
        m_lo = mn_lo; m_hi = mn_hi;

        float sum_lo = 0.f, sum_hi = 0.f;
        #pragma unroll
        for (int j = 0; j < 8; j++) {
            c[j][0] = ex2(c[j][0] - mn_lo);
            c[j][1] = ex2(c[j][1] - mn_lo);
            c[j][2] = ex2(c[j][2] - mn_hi);
            c[j][3] = ex2(c[j][3] - mn_hi);
            sum_lo += c[j][0] + c[j][1];
            sum_hi += c[j][2] + c[j][3];
        }
        sum_lo += __shfl_xor_sync(0xffffffffu, sum_lo, 1);
        sum_lo += __shfl_xor_sync(0xffffffffu, sum_lo, 2);
        sum_hi += __shfl_xor_sync(0xffffffffu, sum_hi, 1);
        sum_hi += __shfl_xor_sync(0xffffffffu, sum_hi, 2);
        l_lo = l_lo * sc_lo + sum_lo;
        l_hi = l_hi * sc_hi + sum_hi;

        #pragma unroll
        for (int j = 0; j < 8; j++) {
            O[j][0] *= sc_lo; O[j][1] *= sc_lo; O[j][2] *= sc_hi; O[j][3] *= sc_hi;
        }

        // ---- pack P fp16 A-frags (C-frag layout == A-frag layout) ----
        uint32_t pf[4][4];
        #pragma unroll
        for (int t = 0; t < 4; t++) {
            const int j0 = 2 * t, j1 = 2 * t + 1;
            pf[t][0] = pack_h2(c[j0][0], c[j0][1]);
            pf[t][1] = pack_h2(c[j0][2], c[j0][3]);
            pf[t][2] = pack_h2(c[j1][0], c[j1][1]);
            pf[t][3] = pack_h2(c[j1][2], c[j1][3]);
        }

        // ---- O += P V ----
        #pragma unroll
        for (int t = 0; t < 4; t++) {
            uint32_t vb[4][4];
            #pragma unroll
            for (int ng = 0; ng < 4; ng++)
                ldmx4(vb[ng], vtB + (uint32_t)((ng * 16 + b_nrow) * FROWB + t * 16 + b_kof) * 2);
            #pragma unroll
            for (int nj = 0; nj < 8; nj++)
                mma16816h(O[nj], pf[t], vb[nj >> 1][(nj & 1) * 2], vb[nj >> 1][(nj & 1) * 2 + 1]);
        }
    }

    // ---- epilogue ----
    const float inv_lo = 1.f / l_lo;
    const float inv_hi = 1.f / l_hi;
    #pragma unroll
    for (int j = 0; j < 8; j++) {
        const int col = h * HEAD + j * 8 + (lane & 3) * 2;
        *(float2*)&out[(size_t)(b * SEQ + r_lo) * H_DIM + col] =
            make_float2(O[j][0] * inv_lo, O[j][1] * inv_lo);
        *(float2*)&out[(size_t)(b * SEQ + r_lo + 8) * H_DIM + col] =
            make_float2(O[j][2] * inv_hi, O[j][3] * inv_hi);
    }
    #undef LOAD_KV
}

// ---------------------------------------------------------------------------
extern "C" void kernel_launch(void* const* d_in, const int* in_sizes, int n_in,
                              void* d_out, int out_size)
{
    const float* x  = (const float*)d_in[0];
    const float* Wq = (const float*)d_in[1];
    const float* bq = (const float*)d_in[2];
    const float* Wk = (const float*)d_in[3];
    const float* bk = (const float*)d_in[4];
    const float* Wv = (const float*)d_in[5];
    const float* bv = (const float*)d_in[6];
    float* out = (float*)d_out;

    cudaFuncSetAttribute(fattn_kernel,
                         cudaFuncAttributeMaxDynamicSharedMemorySize, ATTN_SMEM);

    convert_x_kernel<<<MROWS * H_DIM / 512, 256>>>(x);
    convert_w_kernel<<<NTOT * H_DIM / 512, 256>>>(Wq, Wk, Wv);

    dim3 ggrid(NTOT / 128, MROWS / 128);       // (24, 32)
    qkv_mma_kernel<<<ggrid, 256>>>(bq, bk, bv);

    dim3 vgrid(SEQ / 128, 32);                 // (16, 32)
    convert_v_kernel<<<vgrid, 256>>>();

    dim3 agrid(SEQ / 64, BATCH * NHEADS);      // (32, 32)
    fattn_kernel<<<agrid, 128, ATTN_SMEM>>>(out);
}